// round 1
// baseline (speedup 1.0000x reference)
#include <cuda_runtime.h>
#include <math.h>

#define TOK   8192
#define HD    1024
#define FD    4096
#define ED    8
#define KSEL  2
#define NJOBS (TOK * KSEL)   // 16384, always exact: every token picks exactly 2 experts

// ---------------- device scratch (no allocations allowed) ----------------
__device__ float g_hbuf[(size_t)NJOBS * FD];   // 256 MB: gelu(x@W1+b1) rows
__device__ float g_obuf[(size_t)NJOBS * HD];   // 64 MB:  h@W2+b2 rows
__device__ int   g_jobs_tok[NJOBS];
__device__ int   g_jobs_e[NJOBS];
__device__ float g_jobs_p[NJOBS];
__device__ int   g_cnt[ED];
__device__ int   g_off[ED];
__device__ int   g_fill[ED];
__device__ int   g_topk_e[NJOBS];
__device__ float g_topk_p[NJOBS];

// ---------------- helpers ----------------
__device__ __forceinline__ float block_reduce_sum(float v, float* red) {
    int tid = threadIdx.x;
    red[tid] = v;
    __syncthreads();
#pragma unroll
    for (int o = 128; o > 0; o >>= 1) {
        if (tid < o) red[tid] += red[tid + o];
        __syncthreads();
    }
    float r = red[0];
    __syncthreads();   // make red reusable
    return r;
}

// ---------------- kernel 0: zero routing counters ----------------
__global__ void zero_counts_kernel() {
    if (threadIdx.x < ED) {
        g_cnt[threadIdx.x]  = 0;
        g_fill[threadIdx.x] = 0;
    }
}

// ---------------- kernel 1: gating (LN -> logits -> softmax -> top2) ----------------
__global__ void gate_kernel(const float* __restrict__ x,
                            const float* __restrict__ gn_g,
                            const float* __restrict__ gn_b,
                            const float* __restrict__ gate_w,   // [H, E]
                            const float* __restrict__ gate_b) { // [E]
    int t   = blockIdx.x;
    int tid = threadIdx.x;
    const float4* xr4 = (const float4*)(x + (size_t)t * HD);

    __shared__ float red[256];
    __shared__ float sm_mean, sm_rstd;
    __shared__ float sm_logits[ED];

    float4 xv = xr4[tid];   // 4 contiguous elements per thread: h = tid*4 + i
    float xs[4] = {xv.x, xv.y, xv.z, xv.w};
    float s = 0.f, s2 = 0.f;
#pragma unroll
    for (int i = 0; i < 4; i++) { s += xs[i]; s2 += xs[i] * xs[i]; }

    float tot = block_reduce_sum(s, red);
    if (tid == 0) sm_mean = tot * (1.f / HD);
    float tot2 = block_reduce_sum(s2, red);
    if (tid == 0) {
        float m = sm_mean;
        sm_rstd = rsqrtf(tot2 * (1.f / HD) - m * m + 1e-5f);
    }
    __syncthreads();

    float m = sm_mean, r = sm_rstd;
    float acc[ED];
#pragma unroll
    for (int e = 0; e < ED; e++) acc[e] = 0.f;
#pragma unroll
    for (int i = 0; i < 4; i++) {
        int h = tid * 4 + i;
        float xn = (xs[i] - m) * r * gn_g[h] + gn_b[h];
#pragma unroll
        for (int e = 0; e < ED; e++) acc[e] += xn * gate_w[h * ED + e];
    }
#pragma unroll
    for (int e = 0; e < ED; e++) {
        float le = block_reduce_sum(acc[e], red);
        if (tid == 0) sm_logits[e] = le + gate_b[e];
    }
    __syncthreads();

    if (tid == 0) {
        float l[ED], pr[ED];
        float mx = -1e30f;
#pragma unroll
        for (int e = 0; e < ED; e++) { l[e] = sm_logits[e]; mx = fmaxf(mx, l[e]); }
        float ssum = 0.f;
#pragma unroll
        for (int e = 0; e < ED; e++) { pr[e] = expf(l[e] - mx); ssum += pr[e]; }
        float inv = 1.f / ssum;
#pragma unroll
        for (int e = 0; e < ED; e++) pr[e] *= inv;
        // top-2 (first-index-wins on ties, matching lax.top_k)
        int i0 = 0;
#pragma unroll
        for (int e = 1; e < ED; e++) if (pr[e] > pr[i0]) i0 = e;
        int i1 = (i0 == 0) ? 1 : 0;
#pragma unroll
        for (int e = 0; e < ED; e++) if (e != i0 && pr[e] > pr[i1]) i1 = e;

        float p0 = pr[i0], p1 = pr[i1];
        float dn = 1.f / (p0 + p1 + 1e-9f);
        p0 *= dn; p1 *= dn;

        g_topk_e[t * 2 + 0] = i0;  g_topk_p[t * 2 + 0] = p0;
        g_topk_e[t * 2 + 1] = i1;  g_topk_p[t * 2 + 1] = p1;
        atomicAdd(&g_cnt[i0], 1);
        atomicAdd(&g_cnt[i1], 1);
    }
}

// ---------------- kernel 2: exclusive scan of expert counts ----------------
__global__ void scan_kernel() {
    if (threadIdx.x == 0) {
        int o = 0;
        for (int e = 0; e < ED; e++) { g_off[e] = o; o += g_cnt[e]; }
    }
}

// ---------------- kernel 3: scatter tokens into per-expert segments ----------------
__global__ void scatter_kernel() {
    int t = blockIdx.x * blockDim.x + threadIdx.x;
    if (t >= TOK) return;
#pragma unroll
    for (int k = 0; k < KSEL; k++) {
        int e   = g_topk_e[t * 2 + k];
        int pos = atomicAdd(&g_fill[e], 1);
        int j   = g_off[e] + pos;
        g_jobs_tok[j] = t;
        g_jobs_e[j]   = e;
        g_jobs_p[j]   = g_topk_p[t * 2 + k];
    }
}

// ---------------- grouped SGEMM: C[j, n] = epi(A[j, :] @ W[e] + bias[e]) ----------------
// 128x128 tile, BK=8, 256 threads, 8x8 register tile per thread.
template <int KDIM, int NDIM, bool GATHER, bool DOGELU>
__global__ void __launch_bounds__(256, 2)
gemm_kernel(const float* __restrict__ Ain,   // GATHER: x [T,KDIM]; else contiguous rows [NJOBS,KDIM]
            const float* __restrict__ W,     // [E, KDIM, NDIM]
            const float* __restrict__ bias,  // [E, NDIM]
            float* __restrict__ C) {         // [NJOBS, NDIM]
    int e   = blockIdx.z;
    int cnt = g_cnt[e];
    int m0  = blockIdx.y * 128;
    if (m0 >= cnt) return;
    int off = g_off[e];
    int n0  = blockIdx.x * 128;

    const float* Bw = W + (size_t)e * KDIM * NDIM;
    const float* be = bias + (size_t)e * NDIM;

    __shared__ float As[8][132];   // padded: conflict-free transposed stores
    __shared__ float Bs[8][128];

    int tid = threadIdx.x;

    // A-tile mapping: one float4 per thread
    int arow = tid >> 1;
    int ak   = (tid & 1) * 4;
    bool avalid = (m0 + arow) < cnt;
    const float* Aptr;
    {
        int jg = off + m0 + (avalid ? arow : 0);
        if (GATHER) {
            int tok = g_jobs_tok[jg];
            Aptr = Ain + (size_t)tok * KDIM + ak;
        } else {
            Aptr = Ain + (size_t)jg * KDIM + ak;
        }
    }
    // B-tile mapping: one float4 per thread
    int bk = tid >> 5;
    int bn = (tid & 31) * 4;
    const float* Bptr = Bw + (size_t)bk * NDIM + n0 + bn;

    int tr = tid >> 4;   // 0..15
    int tc = tid & 15;   // 0..15

    float acc[8][8];
#pragma unroll
    for (int i = 0; i < 8; i++)
#pragma unroll
        for (int j = 0; j < 8; j++) acc[i][j] = 0.f;

    for (int k0 = 0; k0 < KDIM; k0 += 8) {
        float4 av = avalid ? *(const float4*)(Aptr + k0) : make_float4(0.f, 0.f, 0.f, 0.f);
        float4 bv = *(const float4*)(Bptr + (size_t)k0 * NDIM);
        __syncthreads();
        As[ak + 0][arow] = av.x;
        As[ak + 1][arow] = av.y;
        As[ak + 2][arow] = av.z;
        As[ak + 3][arow] = av.w;
        *(float4*)&Bs[bk][bn] = bv;
        __syncthreads();
#pragma unroll
        for (int kk = 0; kk < 8; kk++) {
            float a[8], b[8];
            *(float4*)(a)     = *(const float4*)&As[kk][tr * 8];
            *(float4*)(a + 4) = *(const float4*)&As[kk][tr * 8 + 4];
            *(float4*)(b)     = *(const float4*)&Bs[kk][tc * 8];
            *(float4*)(b + 4) = *(const float4*)&Bs[kk][tc * 8 + 4];
#pragma unroll
            for (int i = 0; i < 8; i++)
#pragma unroll
                for (int j = 0; j < 8; j++) acc[i][j] = fmaf(a[i], b[j], acc[i][j]);
        }
    }

    // epilogue: bias (+ exact gelu), vectorized stores
#pragma unroll
    for (int i = 0; i < 8; i++) {
        int mrow = m0 + tr * 8 + i;
        if (mrow < cnt) {
            size_t jg = (size_t)(off + mrow);
            float* Crow = C + jg * NDIM + n0 + tc * 8;
            float o[8];
#pragma unroll
            for (int j = 0; j < 8; j++) {
                float c = acc[i][j] + be[n0 + tc * 8 + j];
                if (DOGELU) c = 0.5f * c * (1.f + erff(c * 0.70710678118654752f));
                o[j] = c;
            }
            *(float4*)(Crow)     = *(float4*)(o);
            *(float4*)(Crow + 4) = *(float4*)(o + 4);
        }
    }
}

// ---------------- kernel 6: LN(out + residual) * p, atomic combine ----------------
__global__ void combine_kernel(const float* __restrict__ x,
                               const float* __restrict__ ln_g,  // [E, H]
                               const float* __restrict__ ln_b,  // [E, H]
                               float* __restrict__ y) {         // [T, H], pre-zeroed
    int j   = blockIdx.x;
    int tid = threadIdx.x;
    int t = g_jobs_tok[j];
    int e = g_jobs_e[j];
    float p = g_jobs_p[j];

    const float4* orow = (const float4*)(g_obuf + (size_t)j * HD);
    const float4* xrow = (const float4*)(x + (size_t)t * HD);

    __shared__ float red[256];
    __shared__ float sm_mean, sm_rstd;

    float4 ov = orow[tid];
    float4 xv = xrow[tid];
    float v[4] = {ov.x + xv.x, ov.y + xv.y, ov.z + xv.z, ov.w + xv.w};
    float s = 0.f, s2 = 0.f;
#pragma unroll
    for (int i = 0; i < 4; i++) { s += v[i]; s2 += v[i] * v[i]; }

    float tot = block_reduce_sum(s, red);
    if (tid == 0) sm_mean = tot * (1.f / HD);
    float tot2 = block_reduce_sum(s2, red);
    if (tid == 0) {
        float m = sm_mean;
        sm_rstd = rsqrtf(tot2 * (1.f / HD) - m * m + 1e-5f);
    }
    __syncthreads();

    float m = sm_mean, r = sm_rstd;
#pragma unroll
    for (int i = 0; i < 4; i++) {
        int h = tid * 4 + i;
        float o = (v[i] - m) * r * ln_g[(size_t)e * HD + h] + ln_b[(size_t)e * HD + h];
        atomicAdd(&y[(size_t)t * HD + h], o * p);   // exactly 2 adds/element -> order-invariant
    }
}

// ---------------- launch ----------------
extern "C" void kernel_launch(void* const* d_in, const int* in_sizes, int n_in,
                              void* d_out, int out_size) {
    const float* x      = (const float*)d_in[0];
    const float* W1     = (const float*)d_in[1];
    const float* b1     = (const float*)d_in[2];
    const float* W2     = (const float*)d_in[3];
    const float* b2     = (const float*)d_in[4];
    const float* ln_g   = (const float*)d_in[5];
    const float* ln_b   = (const float*)d_in[6];
    const float* gn_g   = (const float*)d_in[7];
    const float* gn_b   = (const float*)d_in[8];
    const float* gate_w = (const float*)d_in[9];
    const float* gate_b = (const float*)d_in[10];
    float* y = (float*)d_out;

    float* hbuf_p = nullptr;
    float* obuf_p = nullptr;
    cudaGetSymbolAddress((void**)&hbuf_p, g_hbuf);
    cudaGetSymbolAddress((void**)&obuf_p, g_obuf);

    zero_counts_kernel<<<1, 32>>>();
    gate_kernel<<<TOK, 256>>>(x, gn_g, gn_b, gate_w, gate_b);
    scan_kernel<<<1, 1>>>();
    scatter_kernel<<<TOK / 256, 256>>>();

    // GEMM1: h = gelu(x @ W1[e] + b1[e]),  M<=8192/expert, N=4096, K=1024
    gemm_kernel<HD, FD, true, true>
        <<<dim3(FD / 128, TOK / 128, ED), 256>>>(x, W1, b1, hbuf_p);
    // GEMM2: out = h @ W2[e] + b2[e],      N=1024, K=4096
    gemm_kernel<FD, HD, false, false>
        <<<dim3(HD / 128, TOK / 128, ED), 256>>>(hbuf_p, W2, b2, obuf_p);

    cudaMemsetAsync(d_out, 0, (size_t)out_size * sizeof(float), 0);
    combine_kernel<<<NJOBS, 256>>>(x, ln_g, ln_b, y);
}

// round 4
// speedup vs baseline: 1.9545x; 1.9545x over previous
#include <cuda_runtime.h>
#include <cuda_fp16.h>
#include <math.h>
#include <stdint.h>

#define TOK   8192
#define HD    1024
#define FD    4096
#define ED    8
#define NJOBS (TOK * 2)

// ---------------- device scratch ----------------
__device__ uint32_t g_hbuf[(size_t)NJOBS * FD];   // 256 MB: h as packed (hi16|lo16) half pairs
__device__ float    g_obuf[(size_t)NJOBS * HD];   // 64 MB
__device__ int   g_jobs_tok[NJOBS];
__device__ int   g_jobs_e[NJOBS];
__device__ float g_jobs_p[NJOBS];
__device__ int   g_cnt[ED];
__device__ int   g_off[ED];
__device__ int   g_fill[ED];
__device__ int   g_topk_e[NJOBS];
__device__ float g_topk_p[NJOBS];

// ---------------- PTX helpers (sm_80-class only: ldmatrix + mma.sync) ----------------
__device__ __forceinline__ uint32_t smem_u32(const void* p) {
    uint32_t a;
    asm("{ .reg .u64 t; cvta.to.shared.u64 t, %1; cvt.u32.u64 %0, t; }" : "=r"(a) : "l"(p));
    return a;
}
__device__ __forceinline__ void ldsm_x4(uint32_t* r, uint32_t addr) {
    asm volatile("ldmatrix.sync.aligned.m8n8.x4.shared.b16 {%0,%1,%2,%3}, [%4];"
        : "=r"(r[0]), "=r"(r[1]), "=r"(r[2]), "=r"(r[3]) : "r"(addr));
}
__device__ __forceinline__ void ldsm_x4_t(uint32_t* r, uint32_t addr) {
    asm volatile("ldmatrix.sync.aligned.m8n8.x4.trans.shared.b16 {%0,%1,%2,%3}, [%4];"
        : "=r"(r[0]), "=r"(r[1]), "=r"(r[2]), "=r"(r[3]) : "r"(addr));
}
__device__ __forceinline__ void mma16816(float* d, const uint32_t* a, const uint32_t* b) {
    asm volatile("mma.sync.aligned.m16n8k16.row.col.f32.f16.f16.f32 "
        "{%0,%1,%2,%3}, {%4,%5,%6,%7}, {%8,%9}, {%0,%1,%2,%3};"
        : "+f"(d[0]), "+f"(d[1]), "+f"(d[2]), "+f"(d[3])
        : "r"(a[0]), "r"(a[1]), "r"(a[2]), "r"(a[3]), "r"(b[0]), "r"(b[1]));
}

// pack fp32 -> (hi half | lo half << 16), exact-split representation
__device__ __forceinline__ uint32_t pack_hilo(float c) {
    __half h = __float2half_rn(c);
    __half l = __float2half_rn(c - __half2float(h));
    return (uint32_t)__half_as_ushort(h) | ((uint32_t)__half_as_ushort(l) << 16);
}
__device__ __forceinline__ void split8(const float* f, uint4& hv, uint4& lv) {
    uint32_t hw[4], lw[4];
#pragma unroll
    for (int i = 0; i < 4; i++) {
        __half h0 = __float2half_rn(f[2 * i]),     h1 = __float2half_rn(f[2 * i + 1]);
        __half l0 = __float2half_rn(f[2 * i]     - __half2float(h0));
        __half l1 = __float2half_rn(f[2 * i + 1] - __half2float(h1));
        hw[i] = (uint32_t)__half_as_ushort(h0) | ((uint32_t)__half_as_ushort(h1) << 16);
        lw[i] = (uint32_t)__half_as_ushort(l0) | ((uint32_t)__half_as_ushort(l1) << 16);
    }
    hv = make_uint4(hw[0], hw[1], hw[2], hw[3]);
    lv = make_uint4(lw[0], lw[1], lw[2], lw[3]);
}

// ---------------- reductions ----------------
__device__ __forceinline__ float block_reduce_sum(float v, float* red) {
    int tid = threadIdx.x;
    red[tid] = v;
    __syncthreads();
#pragma unroll
    for (int o = 128; o > 0; o >>= 1) {
        if (tid < o) red[tid] += red[tid + o];
        __syncthreads();
    }
    float r = red[0];
    __syncthreads();
    return r;
}

// ---------------- routing kernels ----------------
__global__ void zero_counts_kernel() {
    if (threadIdx.x < ED) { g_cnt[threadIdx.x] = 0; g_fill[threadIdx.x] = 0; }
}

__global__ void gate_kernel(const float* __restrict__ x,
                            const float* __restrict__ gn_g,
                            const float* __restrict__ gn_b,
                            const float* __restrict__ gate_w,
                            const float* __restrict__ gate_b) {
    int t = blockIdx.x, tid = threadIdx.x;
    const float4* xr4 = (const float4*)(x + (size_t)t * HD);
    __shared__ float red[256];
    __shared__ float sm_mean, sm_rstd;
    __shared__ float sm_logits[ED];

    float4 xv = xr4[tid];
    float xs[4] = {xv.x, xv.y, xv.z, xv.w};
    float s = 0.f, s2 = 0.f;
#pragma unroll
    for (int i = 0; i < 4; i++) { s += xs[i]; s2 += xs[i] * xs[i]; }
    float tot = block_reduce_sum(s, red);
    if (tid == 0) sm_mean = tot * (1.f / HD);
    float tot2 = block_reduce_sum(s2, red);
    if (tid == 0) {
        float m = sm_mean;
        sm_rstd = rsqrtf(tot2 * (1.f / HD) - m * m + 1e-5f);
    }
    __syncthreads();
    float m = sm_mean, r = sm_rstd;
    float acc[ED];
#pragma unroll
    for (int e = 0; e < ED; e++) acc[e] = 0.f;
#pragma unroll
    for (int i = 0; i < 4; i++) {
        int h = tid * 4 + i;
        float xn = (xs[i] - m) * r * gn_g[h] + gn_b[h];
#pragma unroll
        for (int e = 0; e < ED; e++) acc[e] += xn * gate_w[h * ED + e];
    }
#pragma unroll
    for (int e = 0; e < ED; e++) {
        float le = block_reduce_sum(acc[e], red);
        if (tid == 0) sm_logits[e] = le + gate_b[e];
    }
    __syncthreads();
    if (tid == 0) {
        float l[ED], pr[ED];
        float mx = -1e30f;
#pragma unroll
        for (int e = 0; e < ED; e++) { l[e] = sm_logits[e]; mx = fmaxf(mx, l[e]); }
        float ssum = 0.f;
#pragma unroll
        for (int e = 0; e < ED; e++) { pr[e] = expf(l[e] - mx); ssum += pr[e]; }
        float inv = 1.f / ssum;
#pragma unroll
        for (int e = 0; e < ED; e++) pr[e] *= inv;
        int i0 = 0;
#pragma unroll
        for (int e = 1; e < ED; e++) if (pr[e] > pr[i0]) i0 = e;
        int i1 = (i0 == 0) ? 1 : 0;
#pragma unroll
        for (int e = 0; e < ED; e++) if (e != i0 && pr[e] > pr[i1]) i1 = e;
        float p0 = pr[i0], p1 = pr[i1];
        float dn = 1.f / (p0 + p1 + 1e-9f);
        p0 *= dn; p1 *= dn;
        g_topk_e[t * 2 + 0] = i0;  g_topk_p[t * 2 + 0] = p0;
        g_topk_e[t * 2 + 1] = i1;  g_topk_p[t * 2 + 1] = p1;
        atomicAdd(&g_cnt[i0], 1);
        atomicAdd(&g_cnt[i1], 1);
    }
}

__global__ void scan_kernel() {
    if (threadIdx.x == 0) {
        int o = 0;
        for (int e = 0; e < ED; e++) { g_off[e] = o; o += g_cnt[e]; }
    }
}

__global__ void scatter_kernel() {
    int t = blockIdx.x * blockDim.x + threadIdx.x;
    if (t >= TOK) return;
#pragma unroll
    for (int k = 0; k < 2; k++) {
        int e   = g_topk_e[t * 2 + k];
        int pos = atomicAdd(&g_fill[e], 1);
        int j   = g_off[e] + pos;
        g_jobs_tok[j] = t;
        g_jobs_e[j]   = e;
        g_jobs_p[j]   = g_topk_p[t * 2 + k];
    }
}

// ---------------- fp16x3-split grouped GEMM via mma.sync ----------------
// C[M,N] = epi(A @ W[e] + bias[e]); K expanded to 3K in half precision:
//   A' row sections (32 orig k/iter): [hi_a | lo_a | hi_a]   (12 units of 16B, padded to 16)
//   B' row sections:                  [hi_b ; hi_b ; lo_b]   (96 rows x 128 halves)
// Tile: 128m x 128n x 32k, 8 warps (4m x 2n), double-buffered.
// SMEM buffer: A' 128x256B = 32KB, B' 96x256B = 24KB -> 56KB x2 = 112KB + 1KB hdr.
#define BUF_BYTES 57344
#define SMEM_BYTES (1024 + 2 * BUF_BYTES)

template <int KDIM, int NDIM, bool GATHER, bool AHALF, bool DOGELU>
__global__ void __launch_bounds__(256, 1)
gemm_mma(const void* __restrict__ Ain,   // GATHER: x fp32 [T,KDIM]; AHALF: hbuf u32 [NJOBS,KDIM]
         const float* __restrict__ W,    // [E][KDIM][NDIM]  (native layout!)
         const float* __restrict__ bias, // [E][NDIM]
         void* __restrict__ Cout) {      // DOGELU: u32 hbuf; else float obuf
    int e   = blockIdx.z;
    int cnt = g_cnt[e];
    int m0  = blockIdx.x * 128;
    if (m0 >= cnt) return;
    int off = g_off[e];
    int n0  = blockIdx.y * 128;

    extern __shared__ __align__(1024) char smem[];
    uint32_t sb = smem_u32(smem);
    int tid = threadIdx.x, wid = tid >> 5, lane = tid & 31;
    int wm = wid >> 1, wn = wid & 1;
    int* s_tok = (int*)smem;

    if (GATHER && tid < 128) {
        int r = (m0 + tid < cnt) ? tid : 0;
        s_tok[tid] = g_jobs_tok[off + m0 + r];
    }
    __syncthreads();

    const float* We = W + (size_t)e * KDIM * NDIM + n0;
    const float* be = bias + (size_t)e * NDIM;

    // per-thread producer assignments
    // A: 2x (row r = id/4, kgroup kg = id%4 covering 8 orig k)
    int ar_[2], akg_[2];
    const char* aptr_[2];
#pragma unroll
    for (int a = 0; a < 2; a++) {
        int id = tid + a * 256;
        int r = id >> 2, kg = id & 3;
        ar_[a] = r; akg_[a] = kg;
        if (GATHER) {
            aptr_[a] = (const char*)((const float*)Ain + (size_t)s_tok[r] * KDIM + kg * 8);
        } else {
            int rr = (m0 + r < cnt) ? r : 0;
            if (AHALF)
                aptr_[a] = (const char*)((const uint32_t*)Ain + (size_t)(off + m0 + rr) * KDIM + kg * 8);
            else
                aptr_[a] = (const char*)((const float*)Ain + (size_t)(off + m0 + rr) * KDIM + kg * 8);
        }
    }
    // B: 2x (k row = id/16 in [0,32), ngroup ng = id%16 covering 8 n)
    int bk_[2], bng_[2];
#pragma unroll
    for (int a = 0; a < 2; a++) {
        int id = tid + a * 256;
        bk_[a] = id >> 4; bng_[a] = id & 15;
    }

    float acc[16][4];
#pragma unroll
    for (int i = 0; i < 16; i++)
#pragma unroll
        for (int j = 0; j < 4; j++) acc[i][j] = 0.f;

    constexpr int KIT = KDIM / 32;
    // prefetch registers
    float4 afv[2][2];   // fp32 A path
    uint4  ahv[2];      // half2 A path (8 packed pairs = 2x uint4 -> stored as [2][?]); use per-a
    uint4  ahv2[2];
    float4 bfv[2][4];   // B: 2 assignments x (8 n as 2 float4) ... need 16 floats? 8 n = 2 float4

    // ---- prefetch helper (macro-style lambdas) ----
    auto prefetchA = [&](int it) {
#pragma unroll
        for (int a = 0; a < 2; a++) {
            if (AHALF) {
                const uint4* p = (const uint4*)(aptr_[a] + (size_t)it * 32 * 4);
                ahv[a]  = p[0];
                ahv2[a] = p[1];
            } else {
                const float4* p = (const float4*)(aptr_[a] + (size_t)it * 32 * 4);
                afv[a][0] = p[0];
                afv[a][1] = p[1];
            }
        }
    };
    auto prefetchB = [&](int it) {
#pragma unroll
        for (int a = 0; a < 2; a++) {
            const float4* p = (const float4*)(We + (size_t)(it * 32 + bk_[a]) * NDIM + bng_[a] * 8);
            bfv[a][0] = p[0];
            bfv[a][1] = p[1];
        }
    };
    auto storeBuf = [&](int p) {
        char* As = smem + 1024 + p * BUF_BYTES;
        char* Bs = As + 32768;
        // A'
#pragma unroll
        for (int a = 0; a < 2; a++) {
            int r = ar_[a], kg = akg_[a];
            uint4 hv, lv;
            if (AHALF) {
                // packed (hi|lo<<16) pairs: deinterleave 8 pairs -> hi x8, lo x8
                uint32_t q[8] = {ahv[a].x, ahv[a].y, ahv[a].z, ahv[a].w,
                                 ahv2[a].x, ahv2[a].y, ahv2[a].z, ahv2[a].w};
                uint32_t hw[4], lw[4];
#pragma unroll
                for (int i = 0; i < 4; i++) {
                    hw[i] = __byte_perm(q[2 * i], q[2 * i + 1], 0x5410);
                    lw[i] = __byte_perm(q[2 * i], q[2 * i + 1], 0x7632);
                }
                hv = make_uint4(hw[0], hw[1], hw[2], hw[3]);
                lv = make_uint4(lw[0], lw[1], lw[2], lw[3]);
            } else {
                float f[8] = {afv[a][0].x, afv[a][0].y, afv[a][0].z, afv[a][0].w,
                              afv[a][1].x, afv[a][1].y, afv[a][1].z, afv[a][1].w};
                split8(f, hv, lv);
            }
            int sw = (r & 7);
            char* row = As + r * 256;
            *(uint4*)(row + 16 * ((kg)      ^ sw)) = hv;   // sec0 hi
            *(uint4*)(row + 16 * ((4 + kg)  ^ sw)) = lv;   // sec1 lo
            *(uint4*)(row + 16 * ((8 + kg)  ^ sw)) = hv;   // sec2 hi
        }
        // B'
#pragma unroll
        for (int a = 0; a < 2; a++) {
            int k = bk_[a], ng = bng_[a];
            float f[8] = {bfv[a][0].x, bfv[a][0].y, bfv[a][0].z, bfv[a][0].w,
                          bfv[a][1].x, bfv[a][1].y, bfv[a][1].z, bfv[a][1].w};
            uint4 hv, lv;
            split8(f, hv, lv);
            int sw = (k & 7);
            *(uint4*)(Bs + (k)      * 256 + 16 * (ng ^ sw)) = hv;  // sec0 hi
            *(uint4*)(Bs + (32 + k) * 256 + 16 * (ng ^ sw)) = hv;  // sec1 hi
            *(uint4*)(Bs + (64 + k) * 256 + 16 * (ng ^ sw)) = lv;  // sec2 lo
        }
    };

    prefetchA(0); prefetchB(0);
    storeBuf(0);
    __syncthreads();

    int rl = lane & 15, cg = lane >> 4;
    for (int it = 0; it < KIT; it++) {
        int p = it & 1;
        if (it + 1 < KIT) { prefetchA(it + 1); prefetchB(it + 1); }

        uint32_t As = sb + 1024 + p * BUF_BYTES;
        uint32_t Bs = As + 32768;
#pragma unroll
        for (int j = 0; j < 6; j++) {
            uint32_t afr[2][4];
#pragma unroll
            for (int mt = 0; mt < 2; mt++) {
                int r = wm * 32 + mt * 16 + rl;
                ldsm_x4(afr[mt], As + r * 256 + 16 * ((2 * j + cg) ^ (r & 7)));
            }
#pragma unroll
            for (int g = 0; g < 4; g++) {
                uint32_t bfr[4];
                int r = j * 16 + rl;
                int u = wn * 8 + g * 2 + cg;
                ldsm_x4_t(bfr, Bs + r * 256 + 16 * (u ^ (r & 7)));
#pragma unroll
                for (int hh = 0; hh < 2; hh++) {
                    int nt = g * 2 + hh;
#pragma unroll
                    for (int mt = 0; mt < 2; mt++)
                        mma16816(acc[mt * 8 + nt], afr[mt], &bfr[hh * 2]);
                }
            }
        }
        if (it + 1 < KIT) {
            storeBuf(p ^ 1);
            __syncthreads();
        }
    }

    // ---- epilogue ----
#pragma unroll
    for (int mt = 0; mt < 2; mt++) {
#pragma unroll
        for (int nt = 0; nt < 8; nt++) {
            float* d = acc[mt * 8 + nt];
            int nc = n0 + wn * 64 + nt * 8 + 2 * (lane & 3);
            float b0 = be[nc], b1 = be[nc + 1];
            int r0 = m0 + wm * 32 + mt * 16 + (lane >> 2);
            int r1 = r0 + 8;
            float c00 = d[0] + b0, c01 = d[1] + b1;
            float c10 = d[2] + b0, c11 = d[3] + b1;
            if (DOGELU) {
                c00 = 0.5f * c00 * (1.f + erff(c00 * 0.70710678118654752f));
                c01 = 0.5f * c01 * (1.f + erff(c01 * 0.70710678118654752f));
                c10 = 0.5f * c10 * (1.f + erff(c10 * 0.70710678118654752f));
                c11 = 0.5f * c11 * (1.f + erff(c11 * 0.70710678118654752f));
                uint32_t* C = (uint32_t*)Cout;
                if (r0 < cnt) *(uint2*)(C + (size_t)(off + r0) * NDIM + nc) =
                    make_uint2(pack_hilo(c00), pack_hilo(c01));
                if (r1 < cnt) *(uint2*)(C + (size_t)(off + r1) * NDIM + nc) =
                    make_uint2(pack_hilo(c10), pack_hilo(c11));
            } else {
                float* C = (float*)Cout;
                if (r0 < cnt) *(float2*)(C + (size_t)(off + r0) * NDIM + nc) = make_float2(c00, c01);
                if (r1 < cnt) *(float2*)(C + (size_t)(off + r1) * NDIM + nc) = make_float2(c10, c11);
            }
        }
    }
}

// ---------------- combine: LN(out + residual) * p ----------------
__global__ void combine_kernel(const float* __restrict__ x,
                               const float* __restrict__ ln_g,
                               const float* __restrict__ ln_b,
                               float* __restrict__ y) {
    int j = blockIdx.x, tid = threadIdx.x;
    int t = g_jobs_tok[j];
    int e = g_jobs_e[j];
    float p = g_jobs_p[j];
    const float4* orow = (const float4*)(g_obuf + (size_t)j * HD);
    const float4* xrow = (const float4*)(x + (size_t)t * HD);
    __shared__ float red[256];
    __shared__ float sm_mean, sm_rstd;
    float4 ov = orow[tid];
    float4 xv = xrow[tid];
    float v[4] = {ov.x + xv.x, ov.y + xv.y, ov.z + xv.z, ov.w + xv.w};
    float s = 0.f, s2 = 0.f;
#pragma unroll
    for (int i = 0; i < 4; i++) { s += v[i]; s2 += v[i] * v[i]; }
    float tot = block_reduce_sum(s, red);
    if (tid == 0) sm_mean = tot * (1.f / HD);
    float tot2 = block_reduce_sum(s2, red);
    if (tid == 0) {
        float m = sm_mean;
        sm_rstd = rsqrtf(tot2 * (1.f / HD) - m * m + 1e-5f);
    }
    __syncthreads();
    float m = sm_mean, r = sm_rstd;
#pragma unroll
    for (int i = 0; i < 4; i++) {
        int h = tid * 4 + i;
        float o = (v[i] - m) * r * ln_g[(size_t)e * HD + h] + ln_b[(size_t)e * HD + h];
        atomicAdd(&y[(size_t)t * HD + h], o * p);
    }
}

// ---------------- launch ----------------
extern "C" void kernel_launch(void* const* d_in, const int* in_sizes, int n_in,
                              void* d_out, int out_size) {
    const float* x      = (const float*)d_in[0];
    const float* W1     = (const float*)d_in[1];
    const float* b1     = (const float*)d_in[2];
    const float* W2     = (const float*)d_in[3];
    const float* b2     = (const float*)d_in[4];
    const float* ln_g   = (const float*)d_in[5];
    const float* ln_b   = (const float*)d_in[6];
    const float* gn_g   = (const float*)d_in[7];
    const float* gn_b   = (const float*)d_in[8];
    const float* gate_w = (const float*)d_in[9];
    const float* gate_b = (const float*)d_in[10];
    float* y = (float*)d_out;

    void *hbuf_p, *obuf_p;
    cudaGetSymbolAddress(&hbuf_p, g_hbuf);
    cudaGetSymbolAddress(&obuf_p, g_obuf);

    cudaFuncSetAttribute(gemm_mma<HD, FD, true, false, true>,
                         cudaFuncAttributeMaxDynamicSharedMemorySize, SMEM_BYTES);
    cudaFuncSetAttribute(gemm_mma<FD, HD, false, true, false>,
                         cudaFuncAttributeMaxDynamicSharedMemorySize, SMEM_BYTES);

    zero_counts_kernel<<<1, 32>>>();
    gate_kernel<<<TOK, 256>>>(x, gn_g, gn_b, gate_w, gate_b);
    scan_kernel<<<1, 1>>>();
    scatter_kernel<<<TOK / 256, 256>>>();

    // GEMM1: h = gelu(x @ W1[e] + b1[e]); W1 native [E][H][F] is k-major. grid: (m, n, e)
    gemm_mma<HD, FD, true, false, true>
        <<<dim3(TOK / 128, FD / 128, ED), 256, SMEM_BYTES>>>(x, W1, b1, hbuf_p);
    // GEMM2: out = h @ W2[e] + b2[e]; W2 native [E][F][H] is k-major.
    gemm_mma<FD, HD, false, true, false>
        <<<dim3(TOK / 128, HD / 128, ED), 256, SMEM_BYTES>>>(hbuf_p, W2, b2, obuf_p);

    cudaMemsetAsync(d_out, 0, (size_t)out_size * sizeof(float), 0);
    combine_kernel<<<NJOBS, 256>>>(x, ln_g, ln_b, y);
}

// round 6
// speedup vs baseline: 2.5963x; 1.3284x over previous
#include <cuda_runtime.h>
#include <cuda_fp16.h>
#include <math.h>
#include <stdint.h>

#define TOK   8192
#define HD    1024
#define FD    4096
#define ED    8
#define NJOBS (TOK * 2)

// ---------------- device scratch ----------------
__device__ __half g_xhi[(size_t)TOK * HD];
__device__ __half g_xlo[(size_t)TOK * HD];
__device__ __half g_w1hi[(size_t)ED * HD * FD];
__device__ __half g_w1lo[(size_t)ED * HD * FD];
__device__ __half g_w2hi[(size_t)ED * FD * HD];
__device__ __half g_w2lo[(size_t)ED * FD * HD];
__device__ __half g_hhi[(size_t)NJOBS * FD];
__device__ __half g_hlo[(size_t)NJOBS * FD];
__device__ float  g_obuf[(size_t)NJOBS * HD];
__device__ int    g_jobs_tok[NJOBS];
__device__ int    g_jobs_e[NJOBS];
__device__ float  g_jobs_p[NJOBS];
__device__ int    g_cnt[ED];
__device__ int    g_off[ED];
__device__ int    g_fill[ED];
__device__ int    g_topk_e[NJOBS];
__device__ float  g_topk_p[NJOBS];

// ---------------- PTX helpers (sm_80-class only) ----------------
__device__ __forceinline__ uint32_t smem_u32(const void* p) {
    uint32_t a;
    asm("{ .reg .u64 t; cvta.to.shared.u64 t, %1; cvt.u32.u64 %0, t; }" : "=r"(a) : "l"(p));
    return a;
}
__device__ __forceinline__ void ldsm_x4(uint32_t* r, uint32_t addr) {
    asm volatile("ldmatrix.sync.aligned.m8n8.x4.shared.b16 {%0,%1,%2,%3}, [%4];"
        : "=r"(r[0]), "=r"(r[1]), "=r"(r[2]), "=r"(r[3]) : "r"(addr));
}
__device__ __forceinline__ void ldsm_x4_t(uint32_t* r, uint32_t addr) {
    asm volatile("ldmatrix.sync.aligned.m8n8.x4.trans.shared.b16 {%0,%1,%2,%3}, [%4];"
        : "=r"(r[0]), "=r"(r[1]), "=r"(r[2]), "=r"(r[3]) : "r"(addr));
}
__device__ __forceinline__ void mma16816(float* d, const uint32_t* a, const uint32_t* b) {
    asm volatile("mma.sync.aligned.m16n8k16.row.col.f32.f16.f16.f32 "
        "{%0,%1,%2,%3}, {%4,%5,%6,%7}, {%8,%9}, {%0,%1,%2,%3};"
        : "+f"(d[0]), "+f"(d[1]), "+f"(d[2]), "+f"(d[3])
        : "r"(a[0]), "r"(a[1]), "r"(a[2]), "r"(a[3]), "r"(b[0]), "r"(b[1]));
}
__device__ __forceinline__ void cp16(uint32_t dst, const void* src) {
    asm volatile("cp.async.cg.shared.global [%0], [%1], 16;"
        :: "r"(dst), "l"(__cvta_generic_to_global(src)) : "memory");
}
#define CP_COMMIT() asm volatile("cp.async.commit_group;" ::: "memory")
#define CP_WAIT(n)  asm volatile("cp.async.wait_group %0;" :: "n"(n) : "memory")

// ---------------- reductions ----------------
__device__ __forceinline__ float block_reduce_sum(float v, float* red) {
    int tid = threadIdx.x;
    red[tid] = v;
    __syncthreads();
#pragma unroll
    for (int o = 128; o > 0; o >>= 1) {
        if (tid < o) red[tid] += red[tid + o];
        __syncthreads();
    }
    float r = red[0];
    __syncthreads();
    return r;
}

// ---------------- split-convert: fp32 -> (hi, lo) fp16 planes ----------------
__global__ void __launch_bounds__(256) convert_split(const float* __restrict__ src,
                                                     __half* __restrict__ hi,
                                                     __half* __restrict__ lo,
                                                     size_t n4) {
    size_t i = (size_t)blockIdx.x * blockDim.x + threadIdx.x;
    if (i >= n4) return;
    float4 v = ((const float4*)src)[i];
    float f[4] = {v.x, v.y, v.z, v.w};
    uint32_t hw[2], lw[2];
#pragma unroll
    for (int q = 0; q < 2; q++) {
        __half h0 = __float2half_rn(f[2 * q]),     h1 = __float2half_rn(f[2 * q + 1]);
        __half l0 = __float2half_rn(f[2 * q]     - __half2float(h0));
        __half l1 = __float2half_rn(f[2 * q + 1] - __half2float(h1));
        hw[q] = (uint32_t)__half_as_ushort(h0) | ((uint32_t)__half_as_ushort(h1) << 16);
        lw[q] = (uint32_t)__half_as_ushort(l0) | ((uint32_t)__half_as_ushort(l1) << 16);
    }
    ((uint2*)hi)[i] = make_uint2(hw[0], hw[1]);
    ((uint2*)lo)[i] = make_uint2(lw[0], lw[1]);
}

// ---------------- routing kernels ----------------
__global__ void zero_counts_kernel() {
    if (threadIdx.x < ED) { g_cnt[threadIdx.x] = 0; g_fill[threadIdx.x] = 0; }
}

__global__ void gate_kernel(const float* __restrict__ x,
                            const float* __restrict__ gn_g,
                            const float* __restrict__ gn_b,
                            const float* __restrict__ gate_w,
                            const float* __restrict__ gate_b) {
    int t = blockIdx.x, tid = threadIdx.x;
    const float4* xr4 = (const float4*)(x + (size_t)t * HD);
    __shared__ float red[256];
    __shared__ float sm_mean, sm_rstd;
    __shared__ float sm_logits[ED];

    float4 xv = xr4[tid];
    float xs[4] = {xv.x, xv.y, xv.z, xv.w};
    float s = 0.f, s2 = 0.f;
#pragma unroll
    for (int i = 0; i < 4; i++) { s += xs[i]; s2 += xs[i] * xs[i]; }
    float tot = block_reduce_sum(s, red);
    if (tid == 0) sm_mean = tot * (1.f / HD);
    float tot2 = block_reduce_sum(s2, red);
    if (tid == 0) {
        float m = sm_mean;
        sm_rstd = rsqrtf(tot2 * (1.f / HD) - m * m + 1e-5f);
    }
    __syncthreads();
    float m = sm_mean, r = sm_rstd;
    float acc[ED];
#pragma unroll
    for (int e = 0; e < ED; e++) acc[e] = 0.f;
#pragma unroll
    for (int i = 0; i < 4; i++) {
        int h = tid * 4 + i;
        float xn = (xs[i] - m) * r * gn_g[h] + gn_b[h];
#pragma unroll
        for (int e = 0; e < ED; e++) acc[e] += xn * gate_w[h * ED + e];
    }
#pragma unroll
    for (int e = 0; e < ED; e++) {
        float le = block_reduce_sum(acc[e], red);
        if (tid == 0) sm_logits[e] = le + gate_b[e];
    }
    __syncthreads();
    if (tid == 0) {
        float l[ED], pr[ED];
        float mx = -1e30f;
#pragma unroll
        for (int e = 0; e < ED; e++) { l[e] = sm_logits[e]; mx = fmaxf(mx, l[e]); }
        float ssum = 0.f;
#pragma unroll
        for (int e = 0; e < ED; e++) { pr[e] = expf(l[e] - mx); ssum += pr[e]; }
        float inv = 1.f / ssum;
#pragma unroll
        for (int e = 0; e < ED; e++) pr[e] *= inv;
        int i0 = 0;
#pragma unroll
        for (int e = 1; e < ED; e++) if (pr[e] > pr[i0]) i0 = e;
        int i1 = (i0 == 0) ? 1 : 0;
#pragma unroll
        for (int e = 0; e < ED; e++) if (e != i0 && pr[e] > pr[i1]) i1 = e;
        float p0 = pr[i0], p1 = pr[i1];
        float dn = 1.f / (p0 + p1 + 1e-9f);
        p0 *= dn; p1 *= dn;
        g_topk_e[t * 2 + 0] = i0;  g_topk_p[t * 2 + 0] = p0;
        g_topk_e[t * 2 + 1] = i1;  g_topk_p[t * 2 + 1] = p1;
        atomicAdd(&g_cnt[i0], 1);
        atomicAdd(&g_cnt[i1], 1);
    }
}

__global__ void scan_kernel() {
    if (threadIdx.x == 0) {
        int o = 0;
        for (int e = 0; e < ED; e++) { g_off[e] = o; o += g_cnt[e]; }
    }
}

__global__ void scatter_kernel() {
    int t = blockIdx.x * blockDim.x + threadIdx.x;
    if (t >= TOK) return;
#pragma unroll
    for (int k = 0; k < 2; k++) {
        int e   = g_topk_e[t * 2 + k];
        int pos = atomicAdd(&g_fill[e], 1);
        int j   = g_off[e] + pos;
        g_jobs_tok[j] = t;
        g_jobs_e[j]   = e;
        g_jobs_p[j]   = g_topk_p[t * 2 + k];
    }
}

// ---------------- fp16x3-split grouped GEMM, cp.async pipelined ----------------
// Tile 128m x 128n x 32k. 8 warps (4m x 2n). Stage = A(16KB: 128 rows x [hi 64B|lo 64B])
// + B(16KB: 64 k-rows x 256B, rows 0..31 hi plane, 32..63 lo plane). 5 stages.
// 3 MMA passes per k-iter: (Ahi,Bhi), (Alo,Bhi), (Ahi,Blo).
#define STAGES 5
#define STAGE_BYTES 32768
#define SMEM_BYTES (1024 + STAGES * STAGE_BYTES)

template <int KDIM, int NDIM, bool GATHER, bool DOGELU>
__global__ void __launch_bounds__(256, 1)
gemm_mma(const __half* __restrict__ Ahi,  // [rows][KDIM]
         const __half* __restrict__ Alo,
         const __half* __restrict__ Whi,  // [E][KDIM][NDIM]
         const __half* __restrict__ Wlo,
         const float* __restrict__ bias) {
    int e   = blockIdx.z;
    int cnt = g_cnt[e];
    int m0  = blockIdx.x * 128;
    if (m0 >= cnt) return;
    int off = g_off[e];
    int n0  = blockIdx.y * 128;

    extern __shared__ __align__(1024) char smem[];
    uint32_t sb = smem_u32(smem);
    int tid = threadIdx.x, wid = tid >> 5, lane = tid & 31;
    int wm = wid >> 1, wn = wid & 1;
    int* s_tok = (int*)smem;

    if (GATHER && tid < 128) {
        int r = (m0 + tid < cnt) ? tid : 0;
        s_tok[tid] = g_jobs_tok[off + m0 + r];
    }
    __syncthreads();

    const __half* We_hi = Whi + (size_t)e * KDIM * NDIM + n0;
    const __half* We_lo = Wlo + (size_t)e * KDIM * NDIM + n0;
    const float* be = bias + (size_t)e * NDIM;

    // per-thread cp.async assignments (4 A chunks + 4 B chunks of 16B per stage)
    const __half* asrc[4];
    uint32_t adst[4];
#pragma unroll
    for (int q = 0; q < 4; q++) {
        int c = tid + q * 256;
        int r = c >> 3, u = c & 7;
        int row;
        if (GATHER) row = s_tok[r];
        else { int rr = (m0 + r < cnt) ? r : 0; row = off + m0 + rr; }
        const __half* plane = (u < 4) ? Ahi : Alo;
        asrc[q] = plane + (size_t)row * KDIM + (u & 3) * 8;
        adst[q] = (uint32_t)(r * 128 + 16 * (u ^ (r & 7)));
    }
    const __half* bsrc[4];
    uint32_t bdst[4];
#pragma unroll
    for (int q = 0; q < 4; q++) {
        int c = tid + q * 256;
        int kr = c >> 4, u = c & 15, k = kr & 31;
        const __half* plane = (kr < 32) ? We_hi : We_lo;
        bsrc[q] = plane + (size_t)k * NDIM + u * 8;
        bdst[q] = (uint32_t)(16384 + kr * 256 + 16 * (u ^ (kr & 7)));
    }

    auto issue = [&](int s, int it) {
        uint32_t base = sb + 1024 + s * STAGE_BYTES;
#pragma unroll
        for (int q = 0; q < 4; q++) cp16(base + adst[q], asrc[q] + it * 32);
#pragma unroll
        for (int q = 0; q < 4; q++) cp16(base + bdst[q], bsrc[q] + (size_t)it * 32 * NDIM);
    };

    float acc[16][4];
#pragma unroll
    for (int i = 0; i < 16; i++)
#pragma unroll
        for (int j = 0; j < 4; j++) acc[i][j] = 0.f;

    constexpr int KIT = KDIM / 32;
    // prologue: fill STAGES-1 stages
#pragma unroll
    for (int s = 0; s < STAGES - 1; s++) {
        if (s < KIT) issue(s, s);
        CP_COMMIT();
    }

    int rl = lane & 15, cg = lane >> 4;
    for (int it = 0; it < KIT; it++) {
        CP_WAIT(STAGES - 2);
        __syncthreads();
        uint32_t As = sb + 1024 + (it % STAGES) * STAGE_BYTES;
        uint32_t Bs = As + 16384;
#pragma unroll
        for (int pass = 0; pass < 3; pass++) {
            int asec = (pass == 1) ? 1 : 0;   // A lo on pass 1
            int bsec = (pass == 2) ? 1 : 0;   // B lo on pass 2
#pragma unroll
            for (int jj = 0; jj < 2; jj++) {
                uint32_t afr[2][4];
#pragma unroll
                for (int mt = 0; mt < 2; mt++) {
                    int r = wm * 32 + mt * 16 + rl;
                    ldsm_x4(afr[mt], As + r * 128 + 16 * ((asec * 4 + jj * 2 + cg) ^ (r & 7)));
                }
#pragma unroll
                for (int g = 0; g < 4; g++) {
                    uint32_t bfr[4];
                    int rB = bsec * 32 + jj * 16 + rl;
                    ldsm_x4_t(bfr, Bs + rB * 256 + 16 * ((wn * 8 + g * 2 + cg) ^ (rB & 7)));
#pragma unroll
                    for (int hh = 0; hh < 2; hh++) {
                        int nt = g * 2 + hh;
#pragma unroll
                        for (int mt = 0; mt < 2; mt++)
                            mma16816(acc[mt * 8 + nt], afr[mt], &bfr[hh * 2]);
                    }
                }
            }
        }
        int nxt = it + STAGES - 1;
        if (nxt < KIT) issue(nxt % STAGES, nxt);
        CP_COMMIT();
    }

    // ---- epilogue ----
#pragma unroll
    for (int mt = 0; mt < 2; mt++) {
#pragma unroll
        for (int nt = 0; nt < 8; nt++) {
            float* d = acc[mt * 8 + nt];
            int nc = n0 + wn * 64 + nt * 8 + 2 * (lane & 3);
            float b0 = be[nc], b1 = be[nc + 1];
            int r0 = m0 + wm * 32 + mt * 16 + (lane >> 2);
            int r1 = r0 + 8;
            float c00 = d[0] + b0, c01 = d[1] + b1;
            float c10 = d[2] + b0, c11 = d[3] + b1;
            if (DOGELU) {
                c00 = 0.5f * c00 * (1.f + erff(c00 * 0.70710678118654752f));
                c01 = 0.5f * c01 * (1.f + erff(c01 * 0.70710678118654752f));
                c10 = 0.5f * c10 * (1.f + erff(c10 * 0.70710678118654752f));
                c11 = 0.5f * c11 * (1.f + erff(c11 * 0.70710678118654752f));
                // write h as hi/lo fp16 planes
                auto wr = [&](int rr, float a, float b) {
                    size_t base = (size_t)(off + rr) * NDIM + nc;
                    __half h0 = __float2half_rn(a), h1 = __float2half_rn(b);
                    __half l0 = __float2half_rn(a - __half2float(h0));
                    __half l1 = __float2half_rn(b - __half2float(h1));
                    *(uint32_t*)(g_hhi + base) =
                        (uint32_t)__half_as_ushort(h0) | ((uint32_t)__half_as_ushort(h1) << 16);
                    *(uint32_t*)(g_hlo + base) =
                        (uint32_t)__half_as_ushort(l0) | ((uint32_t)__half_as_ushort(l1) << 16);
                };
                if (r0 < cnt) wr(r0, c00, c01);
                if (r1 < cnt) wr(r1, c10, c11);
            } else {
                if (r0 < cnt) *(float2*)(g_obuf + (size_t)(off + r0) * NDIM + nc) = make_float2(c00, c01);
                if (r1 < cnt) *(float2*)(g_obuf + (size_t)(off + r1) * NDIM + nc) = make_float2(c10, c11);
            }
        }
    }
}

// ---------------- combine: LN(out + residual) * p ----------------
__global__ void combine_kernel(const float* __restrict__ x,
                               const float* __restrict__ ln_g,
                               const float* __restrict__ ln_b,
                               float* __restrict__ y) {
    int j = blockIdx.x, tid = threadIdx.x;
    int t = g_jobs_tok[j];
    int e = g_jobs_e[j];
    float p = g_jobs_p[j];
    const float4* orow = (const float4*)(g_obuf + (size_t)j * HD);
    const float4* xrow = (const float4*)(x + (size_t)t * HD);
    __shared__ float red[256];
    __shared__ float sm_mean, sm_rstd;
    float4 ov = orow[tid];
    float4 xv = xrow[tid];
    float v[4] = {ov.x + xv.x, ov.y + xv.y, ov.z + xv.z, ov.w + xv.w};
    float s = 0.f, s2 = 0.f;
#pragma unroll
    for (int i = 0; i < 4; i++) { s += v[i]; s2 += v[i] * v[i]; }
    float tot = block_reduce_sum(s, red);
    if (tid == 0) sm_mean = tot * (1.f / HD);
    float tot2 = block_reduce_sum(s2, red);
    if (tid == 0) {
        float m = sm_mean;
        sm_rstd = rsqrtf(tot2 * (1.f / HD) - m * m + 1e-5f);
    }
    __syncthreads();
    float m = sm_mean, r = sm_rstd;
#pragma unroll
    for (int i = 0; i < 4; i++) {
        int h = tid * 4 + i;
        float o = (v[i] - m) * r * ln_g[(size_t)e * HD + h] + ln_b[(size_t)e * HD + h];
        atomicAdd(&y[(size_t)t * HD + h], o * p);
    }
}

// ---------------- launch ----------------
extern "C" void kernel_launch(void* const* d_in, const int* in_sizes, int n_in,
                              void* d_out, int out_size) {
    const float* x      = (const float*)d_in[0];
    const float* W1     = (const float*)d_in[1];
    const float* b1     = (const float*)d_in[2];
    const float* W2     = (const float*)d_in[3];
    const float* b2     = (const float*)d_in[4];
    const float* ln_g   = (const float*)d_in[5];
    const float* ln_b   = (const float*)d_in[6];
    const float* gn_g   = (const float*)d_in[7];
    const float* gn_b   = (const float*)d_in[8];
    const float* gate_w = (const float*)d_in[9];
    const float* gate_b = (const float*)d_in[10];
    float* y = (float*)d_out;

    __half *xhi, *xlo, *w1hi, *w1lo, *w2hi, *w2lo;
    cudaGetSymbolAddress((void**)&xhi,  g_xhi);
    cudaGetSymbolAddress((void**)&xlo,  g_xlo);
    cudaGetSymbolAddress((void**)&w1hi, g_w1hi);
    cudaGetSymbolAddress((void**)&w1lo, g_w1lo);
    cudaGetSymbolAddress((void**)&w2hi, g_w2hi);
    cudaGetSymbolAddress((void**)&w2lo, g_w2lo);

    cudaFuncSetAttribute(gemm_mma<HD, FD, true, true>,
                         cudaFuncAttributeMaxDynamicSharedMemorySize, SMEM_BYTES);
    cudaFuncSetAttribute(gemm_mma<FD, HD, false, false>,
                         cudaFuncAttributeMaxDynamicSharedMemorySize, SMEM_BYTES);

    // routing (independent of converts)
    zero_counts_kernel<<<1, 32>>>();
    gate_kernel<<<TOK, 256>>>(x, gn_g, gn_b, gate_w, gate_b);
    scan_kernel<<<1, 1>>>();
    scatter_kernel<<<TOK / 256, 256>>>();

    // pre-split operands into fp16 hi/lo planes
    {
        size_t n4;
        n4 = (size_t)TOK * HD / 4;
        convert_split<<<(unsigned)((n4 + 255) / 256), 256>>>(x, xhi, xlo, n4);
        n4 = (size_t)ED * HD * FD / 4;
        convert_split<<<(unsigned)((n4 + 255) / 256), 256>>>(W1, w1hi, w1lo, n4);
        n4 = (size_t)ED * FD * HD / 4;
        convert_split<<<(unsigned)((n4 + 255) / 256), 256>>>(W2, w2hi, w2lo, n4);
    }

    // GEMM1: h = gelu(x @ W1[e] + b1[e]); W1 native [E][H][F] is k-major.
    gemm_mma<HD, FD, true, true>
        <<<dim3(TOK / 128, FD / 128, ED), 256, SMEM_BYTES>>>(xhi, xlo, w1hi, w1lo, b1);
    // GEMM2: out = h @ W2[e] + b2[e]; W2 native [E][F][H] is k-major.
    __half *hhi, *hlo;
    cudaGetSymbolAddress((void**)&hhi, g_hhi);
    cudaGetSymbolAddress((void**)&hlo, g_hlo);
    gemm_mma<FD, HD, false, false>
        <<<dim3(TOK / 128, HD / 128, ED), 256, SMEM_BYTES>>>(hhi, hlo, w2hi, w2lo, b2);

    cudaMemsetAsync(d_out, 0, (size_t)out_size * sizeof(float), 0);
    combine_kernel<<<NJOBS, 256>>>(x, ln_g, ln_b, y);
}

// round 7
// speedup vs baseline: 2.8155x; 1.0844x over previous
#include <cuda_runtime.h>
#include <cuda_fp16.h>
#include <math.h>
#include <stdint.h>

#define TOK   8192
#define HD    1024
#define FD    4096
#define ED    8
#define NJOBS (TOK * 2)

// ---------------- device scratch ----------------
__device__ __half g_xhi[(size_t)TOK * HD];
__device__ __half g_xlo[(size_t)TOK * HD];
__device__ __half g_w1hi[(size_t)ED * HD * FD];
__device__ __half g_w1lo[(size_t)ED * HD * FD];
__device__ __half g_w2hi[(size_t)ED * FD * HD];
__device__ __half g_w2lo[(size_t)ED * FD * HD];
__device__ __half g_hhi[(size_t)NJOBS * FD];
__device__ __half g_hlo[(size_t)NJOBS * FD];
__device__ float  g_obuf[(size_t)NJOBS * HD];
__device__ int    g_jobs_tok[NJOBS];
__device__ int    g_jobs_e[NJOBS];
__device__ float  g_jobs_p[NJOBS];
__device__ int    g_cnt[ED];
__device__ int    g_off[ED];
__device__ int    g_fill[ED];
__device__ int    g_topk_e[NJOBS];
__device__ float  g_topk_p[NJOBS];

// ---------------- PTX helpers (sm_80-class only) ----------------
__device__ __forceinline__ uint32_t smem_u32(const void* p) {
    uint32_t a;
    asm("{ .reg .u64 t; cvta.to.shared.u64 t, %1; cvt.u32.u64 %0, t; }" : "=r"(a) : "l"(p));
    return a;
}
__device__ __forceinline__ void ldsm_x4(uint32_t* r, uint32_t addr) {
    asm volatile("ldmatrix.sync.aligned.m8n8.x4.shared.b16 {%0,%1,%2,%3}, [%4];"
        : "=r"(r[0]), "=r"(r[1]), "=r"(r[2]), "=r"(r[3]) : "r"(addr));
}
__device__ __forceinline__ void ldsm_x4_t(uint32_t* r, uint32_t addr) {
    asm volatile("ldmatrix.sync.aligned.m8n8.x4.trans.shared.b16 {%0,%1,%2,%3}, [%4];"
        : "=r"(r[0]), "=r"(r[1]), "=r"(r[2]), "=r"(r[3]) : "r"(addr));
}
__device__ __forceinline__ void mma16816(float* d, const uint32_t* a, const uint32_t* b) {
    asm volatile("mma.sync.aligned.m16n8k16.row.col.f32.f16.f16.f32 "
        "{%0,%1,%2,%3}, {%4,%5,%6,%7}, {%8,%9}, {%0,%1,%2,%3};"
        : "+f"(d[0]), "+f"(d[1]), "+f"(d[2]), "+f"(d[3])
        : "r"(a[0]), "r"(a[1]), "r"(a[2]), "r"(a[3]), "r"(b[0]), "r"(b[1]));
}
__device__ __forceinline__ void cp16(uint32_t dst, const void* src) {
    asm volatile("cp.async.cg.shared.global [%0], [%1], 16;"
        :: "r"(dst), "l"(__cvta_generic_to_global(src)) : "memory");
}
#define CP_COMMIT() asm volatile("cp.async.commit_group;" ::: "memory")
#define CP_WAIT(n)  asm volatile("cp.async.wait_group %0;" :: "n"(n) : "memory")

// ---------------- reductions ----------------
__device__ __forceinline__ float block_reduce_sum(float v, float* red) {
    int tid = threadIdx.x;
    red[tid] = v;
    __syncthreads();
#pragma unroll
    for (int o = 128; o > 0; o >>= 1) {
        if (tid < o) red[tid] += red[tid + o];
        __syncthreads();
    }
    float r = red[0];
    __syncthreads();
    return r;
}

// ---------------- split-convert: fp32 -> (hi, lo) fp16 planes ----------------
__global__ void __launch_bounds__(256) convert_split(const float* __restrict__ src,
                                                     __half* __restrict__ hi,
                                                     __half* __restrict__ lo,
                                                     size_t n4) {
    size_t i = (size_t)blockIdx.x * blockDim.x + threadIdx.x;
    if (i >= n4) return;
    float4 v = ((const float4*)src)[i];
    float f[4] = {v.x, v.y, v.z, v.w};
    uint32_t hw[2], lw[2];
#pragma unroll
    for (int q = 0; q < 2; q++) {
        __half h0 = __float2half_rn(f[2 * q]),     h1 = __float2half_rn(f[2 * q + 1]);
        __half l0 = __float2half_rn(f[2 * q]     - __half2float(h0));
        __half l1 = __float2half_rn(f[2 * q + 1] - __half2float(h1));
        hw[q] = (uint32_t)__half_as_ushort(h0) | ((uint32_t)__half_as_ushort(h1) << 16);
        lw[q] = (uint32_t)__half_as_ushort(l0) | ((uint32_t)__half_as_ushort(l1) << 16);
    }
    ((uint2*)hi)[i] = make_uint2(hw[0], hw[1]);
    ((uint2*)lo)[i] = make_uint2(lw[0], lw[1]);
}

// ---------------- routing kernels ----------------
__global__ void zero_counts_kernel() {
    if (threadIdx.x < ED) { g_cnt[threadIdx.x] = 0; g_fill[threadIdx.x] = 0; }
}

__global__ void gate_kernel(const float* __restrict__ x,
                            const float* __restrict__ gn_g,
                            const float* __restrict__ gn_b,
                            const float* __restrict__ gate_w,
                            const float* __restrict__ gate_b) {
    int t = blockIdx.x, tid = threadIdx.x;
    const float4* xr4 = (const float4*)(x + (size_t)t * HD);
    __shared__ float red[256];
    __shared__ float sm_mean, sm_rstd;
    __shared__ float sm_logits[ED];

    float4 xv = xr4[tid];
    float xs[4] = {xv.x, xv.y, xv.z, xv.w};
    float s = 0.f, s2 = 0.f;
#pragma unroll
    for (int i = 0; i < 4; i++) { s += xs[i]; s2 += xs[i] * xs[i]; }
    float tot = block_reduce_sum(s, red);
    if (tid == 0) sm_mean = tot * (1.f / HD);
    float tot2 = block_reduce_sum(s2, red);
    if (tid == 0) {
        float m = sm_mean;
        sm_rstd = rsqrtf(tot2 * (1.f / HD) - m * m + 1e-5f);
    }
    __syncthreads();
    float m = sm_mean, r = sm_rstd;
    float acc[ED];
#pragma unroll
    for (int e = 0; e < ED; e++) acc[e] = 0.f;
#pragma unroll
    for (int i = 0; i < 4; i++) {
        int h = tid * 4 + i;
        float xn = (xs[i] - m) * r * gn_g[h] + gn_b[h];
#pragma unroll
        for (int e = 0; e < ED; e++) acc[e] += xn * gate_w[h * ED + e];
    }
#pragma unroll
    for (int e = 0; e < ED; e++) {
        float le = block_reduce_sum(acc[e], red);
        if (tid == 0) sm_logits[e] = le + gate_b[e];
    }
    __syncthreads();
    if (tid == 0) {
        float l[ED], pr[ED];
        float mx = -1e30f;
#pragma unroll
        for (int e = 0; e < ED; e++) { l[e] = sm_logits[e]; mx = fmaxf(mx, l[e]); }
        float ssum = 0.f;
#pragma unroll
        for (int e = 0; e < ED; e++) { pr[e] = expf(l[e] - mx); ssum += pr[e]; }
        float inv = 1.f / ssum;
#pragma unroll
        for (int e = 0; e < ED; e++) pr[e] *= inv;
        int i0 = 0;
#pragma unroll
        for (int e = 1; e < ED; e++) if (pr[e] > pr[i0]) i0 = e;
        int i1 = (i0 == 0) ? 1 : 0;
#pragma unroll
        for (int e = 0; e < ED; e++) if (e != i0 && pr[e] > pr[i1]) i1 = e;
        float p0 = pr[i0], p1 = pr[i1];
        float dn = 1.f / (p0 + p1 + 1e-9f);
        p0 *= dn; p1 *= dn;
        g_topk_e[t * 2 + 0] = i0;  g_topk_p[t * 2 + 0] = p0;
        g_topk_e[t * 2 + 1] = i1;  g_topk_p[t * 2 + 1] = p1;
        atomicAdd(&g_cnt[i0], 1);
        atomicAdd(&g_cnt[i1], 1);
    }
}

__global__ void scan_kernel() {
    if (threadIdx.x == 0) {
        int o = 0;
        for (int e = 0; e < ED; e++) { g_off[e] = o; o += g_cnt[e]; }
    }
}

__global__ void scatter_kernel() {
    int t = blockIdx.x * blockDim.x + threadIdx.x;
    if (t >= TOK) return;
#pragma unroll
    for (int k = 0; k < 2; k++) {
        int e   = g_topk_e[t * 2 + k];
        int pos = atomicAdd(&g_fill[e], 1);
        int j   = g_off[e] + pos;
        g_jobs_tok[j] = t;
        g_jobs_e[j]   = e;
        g_jobs_p[j]   = g_topk_p[t * 2 + k];
    }
}

// ---------------- fp16x3-split grouped GEMM, 128m x 256n tile ----------------
// 8 warps = 2m x 4n; per-warp 64m x 64n (acc[4][8][4] = 128 regs).
// Stage = A 16KB (128 rows x [hi 32k | lo 32k] halves, 128B/row)
//       + B 32KB ([2 planes][32 k][256 n] halves, 512B/k-row, swizzled per 128B block).
// 3 stages = 144KB. 3 MMA passes per k-iter with hoisted fragments:
//   load A_hi,A_lo,B_hi -> A_hi*B_hi, A_lo*B_hi -> load B_lo -> A_hi*B_lo.
#define STAGES 3
#define STAGE_BYTES 49152
#define SMEM_BYTES (1024 + STAGES * STAGE_BYTES)

template <int KDIM, int NDIM, bool GATHER, bool DOGELU>
__global__ void __launch_bounds__(256, 1)
gemm_mma(const __half* __restrict__ Ahi,  // [rows][KDIM]
         const __half* __restrict__ Alo,
         const __half* __restrict__ Whi,  // [E][KDIM][NDIM]
         const __half* __restrict__ Wlo,
         const float* __restrict__ bias) {
    int e   = blockIdx.z;
    int cnt = g_cnt[e];
    int m0  = blockIdx.x * 128;
    if (m0 >= cnt) return;
    int off = g_off[e];
    int n0  = blockIdx.y * 256;

    extern __shared__ __align__(1024) char smem[];
    uint32_t sb = smem_u32(smem);
    int tid = threadIdx.x, wid = tid >> 5, lane = tid & 31;
    int wm = wid >> 2, wn = wid & 3;   // 2m x 4n warp grid
    int* s_tok = (int*)smem;

    if (GATHER && tid < 128) {
        int r = (m0 + tid < cnt) ? tid : 0;
        s_tok[tid] = g_jobs_tok[off + m0 + r];
    }
    __syncthreads();

    const __half* We_hi = Whi + (size_t)e * KDIM * NDIM + n0;
    const __half* We_lo = Wlo + (size_t)e * KDIM * NDIM + n0;
    const float* be = bias + (size_t)e * NDIM;

    // ---- A producer: 4 chunks/thread. u = tid&7 (const), rows r = tid/8 + q*32.
    int au = tid & 7;
    uint32_t aswz = 16u * (uint32_t)(au ^ ((tid >> 3) & 7));   // r&7 == (tid>>3)&7 for all q
    const __half* aplane = (au < 4) ? Ahi : Alo;
    int acol = (au & 3) * 8;
    const __half* asrc[4];
    uint32_t adst[4];
#pragma unroll
    for (int q = 0; q < 4; q++) {
        int r = (tid >> 3) + q * 32;
        int row;
        if (GATHER) row = s_tok[r];
        else { int rr = (m0 + r < cnt) ? r : 0; row = off + m0 + rr; }
        asrc[q] = aplane + (size_t)row * KDIM + acol;
        adst[q] = (uint32_t)(r * 128) + aswz;
    }
    // ---- B producer: 8 chunks/thread. u = tid&31 (const), k = tid/32 + qq*8, plane = q>>2.
    int bu = tid & 31, bk0 = tid >> 5;
    uint32_t bswz = (uint32_t)((bu >> 3) * 128 + 16 * ((bu & 7) ^ (bk0 & 7)));
    const __half* bsrc_hi = We_hi + (size_t)bk0 * NDIM + bu * 8;
    const __half* bsrc_lo = We_lo + (size_t)bk0 * NDIM + bu * 8;

    auto issue = [&](int s, int it) {
        uint32_t base = sb + 1024 + s * STAGE_BYTES;
#pragma unroll
        for (int q = 0; q < 4; q++) cp16(base + adst[q], asrc[q] + it * 32);
        uint32_t bb = base + 16384;
        size_t koff = (size_t)it * 32 * NDIM;
#pragma unroll
        for (int qq = 0; qq < 4; qq++)
            cp16(bb + (uint32_t)((bk0 + qq * 8) * 512) + bswz,
                 bsrc_hi + koff + (size_t)(qq * 8) * NDIM);
#pragma unroll
        for (int qq = 0; qq < 4; qq++)
            cp16(bb + 16384u + (uint32_t)((bk0 + qq * 8) * 512) + bswz,
                 bsrc_lo + koff + (size_t)(qq * 8) * NDIM);
    };

    float acc[32][4];
#pragma unroll
    for (int i = 0; i < 32; i++)
#pragma unroll
        for (int j = 0; j < 4; j++) acc[i][j] = 0.f;

    constexpr int KIT = KDIM / 32;
#pragma unroll
    for (int s = 0; s < STAGES - 1; s++) {
        issue(s, s);
        CP_COMMIT();
    }

    int rl = lane & 15, cg = lane >> 4;
    for (int it = 0; it < KIT; it++) {
        CP_WAIT(STAGES - 2);
        __syncthreads();
        uint32_t As = sb + 1024 + (it % STAGES) * STAGE_BYTES;
        uint32_t Bs = As + 16384;
#pragma unroll
        for (int jj = 0; jj < 2; jj++) {
            // hoisted A fragments: both sections
            uint32_t afr[2][4][4];
#pragma unroll
            for (int asec = 0; asec < 2; asec++)
#pragma unroll
                for (int mt = 0; mt < 4; mt++) {
                    int r = wm * 64 + mt * 16 + rl;
                    ldsm_x4(afr[asec][mt],
                            As + r * 128 + 16 * ((asec * 4 + jj * 2 + cg) ^ (r & 7)));
                }
            int rB = jj * 16 + rl;
            uint32_t brow = Bs + rB * 512 + wn * 128;
            uint32_t bx = 16u * (uint32_t)(((2 * 0 + cg)) ^ (rB & 7));  // recomputed per g below
            (void)bx;
            uint32_t bfr[4][4];
            // B hi plane
#pragma unroll
            for (int g = 0; g < 4; g++)
                ldsm_x4_t(bfr[g], brow + 16 * ((g * 2 + cg) ^ (rB & 7)));
#pragma unroll
            for (int mt = 0; mt < 4; mt++)
#pragma unroll
                for (int g = 0; g < 4; g++)
#pragma unroll
                    for (int hh = 0; hh < 2; hh++)
                        mma16816(acc[mt * 8 + g * 2 + hh], afr[0][mt], &bfr[g][hh * 2]);
#pragma unroll
            for (int mt = 0; mt < 4; mt++)
#pragma unroll
                for (int g = 0; g < 4; g++)
#pragma unroll
                    for (int hh = 0; hh < 2; hh++)
                        mma16816(acc[mt * 8 + g * 2 + hh], afr[1][mt], &bfr[g][hh * 2]);
            // B lo plane (overwrite fragments)
#pragma unroll
            for (int g = 0; g < 4; g++)
                ldsm_x4_t(bfr[g], brow + 16384 + 16 * ((g * 2 + cg) ^ (rB & 7)));
#pragma unroll
            for (int mt = 0; mt < 4; mt++)
#pragma unroll
                for (int g = 0; g < 4; g++)
#pragma unroll
                    for (int hh = 0; hh < 2; hh++)
                        mma16816(acc[mt * 8 + g * 2 + hh], afr[0][mt], &bfr[g][hh * 2]);
        }
        int nxt = it + STAGES - 1;
        if (nxt < KIT) issue(nxt % STAGES, nxt);
        CP_COMMIT();
    }

    // ---- epilogue ----
#pragma unroll
    for (int mt = 0; mt < 4; mt++) {
#pragma unroll
        for (int nt = 0; nt < 8; nt++) {
            float* d = acc[mt * 8 + nt];
            int nc = n0 + wn * 64 + nt * 8 + 2 * (lane & 3);
            float b0 = be[nc], b1 = be[nc + 1];
            int r0 = m0 + wm * 64 + mt * 16 + (lane >> 2);
            int r1 = r0 + 8;
            float c00 = d[0] + b0, c01 = d[1] + b1;
            float c10 = d[2] + b0, c11 = d[3] + b1;
            if (DOGELU) {
                c00 = 0.5f * c00 * (1.f + erff(c00 * 0.70710678118654752f));
                c01 = 0.5f * c01 * (1.f + erff(c01 * 0.70710678118654752f));
                c10 = 0.5f * c10 * (1.f + erff(c10 * 0.70710678118654752f));
                c11 = 0.5f * c11 * (1.f + erff(c11 * 0.70710678118654752f));
                auto wr = [&](int rr, float a, float b) {
                    size_t base = (size_t)(off + rr) * NDIM + nc;
                    __half h0 = __float2half_rn(a), h1 = __float2half_rn(b);
                    __half l0 = __float2half_rn(a - __half2float(h0));
                    __half l1 = __float2half_rn(b - __half2float(h1));
                    *(uint32_t*)(g_hhi + base) =
                        (uint32_t)__half_as_ushort(h0) | ((uint32_t)__half_as_ushort(h1) << 16);
                    *(uint32_t*)(g_hlo + base) =
                        (uint32_t)__half_as_ushort(l0) | ((uint32_t)__half_as_ushort(l1) << 16);
                };
                if (r0 < cnt) wr(r0, c00, c01);
                if (r1 < cnt) wr(r1, c10, c11);
            } else {
                if (r0 < cnt) *(float2*)(g_obuf + (size_t)(off + r0) * NDIM + nc) = make_float2(c00, c01);
                if (r1 < cnt) *(float2*)(g_obuf + (size_t)(off + r1) * NDIM + nc) = make_float2(c10, c11);
            }
        }
    }
}

// ---------------- combine: LN(out + residual) * p ----------------
__global__ void combine_kernel(const float* __restrict__ x,
                               const float* __restrict__ ln_g,
                               const float* __restrict__ ln_b,
                               float* __restrict__ y) {
    int j = blockIdx.x, tid = threadIdx.x;
    int t = g_jobs_tok[j];
    int e = g_jobs_e[j];
    float p = g_jobs_p[j];
    const float4* orow = (const float4*)(g_obuf + (size_t)j * HD);
    const float4* xrow = (const float4*)(x + (size_t)t * HD);
    __shared__ float red[256];
    __shared__ float sm_mean, sm_rstd;
    float4 ov = orow[tid];
    float4 xv = xrow[tid];
    float v[4] = {ov.x + xv.x, ov.y + xv.y, ov.z + xv.z, ov.w + xv.w};
    float s = 0.f, s2 = 0.f;
#pragma unroll
    for (int i = 0; i < 4; i++) { s += v[i]; s2 += v[i] * v[i]; }
    float tot = block_reduce_sum(s, red);
    if (tid == 0) sm_mean = tot * (1.f / HD);
    float tot2 = block_reduce_sum(s2, red);
    if (tid == 0) {
        float m = sm_mean;
        sm_rstd = rsqrtf(tot2 * (1.f / HD) - m * m + 1e-5f);
    }
    __syncthreads();
    float m = sm_mean, r = sm_rstd;
#pragma unroll
    for (int i = 0; i < 4; i++) {
        int h = tid * 4 + i;
        float o = (v[i] - m) * r * ln_g[(size_t)e * HD + h] + ln_b[(size_t)e * HD + h];
        atomicAdd(&y[(size_t)t * HD + h], o * p);
    }
}

// ---------------- launch ----------------
extern "C" void kernel_launch(void* const* d_in, const int* in_sizes, int n_in,
                              void* d_out, int out_size) {
    const float* x      = (const float*)d_in[0];
    const float* W1     = (const float*)d_in[1];
    const float* b1     = (const float*)d_in[2];
    const float* W2     = (const float*)d_in[3];
    const float* b2     = (const float*)d_in[4];
    const float* ln_g   = (const float*)d_in[5];
    const float* ln_b   = (const float*)d_in[6];
    const float* gn_g   = (const float*)d_in[7];
    const float* gn_b   = (const float*)d_in[8];
    const float* gate_w = (const float*)d_in[9];
    const float* gate_b = (const float*)d_in[10];
    float* y = (float*)d_out;

    __half *xhi, *xlo, *w1hi, *w1lo, *w2hi, *w2lo, *hhi, *hlo;
    cudaGetSymbolAddress((void**)&xhi,  g_xhi);
    cudaGetSymbolAddress((void**)&xlo,  g_xlo);
    cudaGetSymbolAddress((void**)&w1hi, g_w1hi);
    cudaGetSymbolAddress((void**)&w1lo, g_w1lo);
    cudaGetSymbolAddress((void**)&w2hi, g_w2hi);
    cudaGetSymbolAddress((void**)&w2lo, g_w2lo);
    cudaGetSymbolAddress((void**)&hhi,  g_hhi);
    cudaGetSymbolAddress((void**)&hlo,  g_hlo);

    cudaFuncSetAttribute(gemm_mma<HD, FD, true, true>,
                         cudaFuncAttributeMaxDynamicSharedMemorySize, SMEM_BYTES);
    cudaFuncSetAttribute(gemm_mma<FD, HD, false, false>,
                         cudaFuncAttributeMaxDynamicSharedMemorySize, SMEM_BYTES);

    // routing (independent of converts)
    zero_counts_kernel<<<1, 32>>>();
    gate_kernel<<<TOK, 256>>>(x, gn_g, gn_b, gate_w, gate_b);
    scan_kernel<<<1, 1>>>();
    scatter_kernel<<<TOK / 256, 256>>>();

    // pre-split operands into fp16 hi/lo planes
    {
        size_t n4;
        n4 = (size_t)TOK * HD / 4;
        convert_split<<<(unsigned)((n4 + 255) / 256), 256>>>(x, xhi, xlo, n4);
        n4 = (size_t)ED * HD * FD / 4;
        convert_split<<<(unsigned)((n4 + 255) / 256), 256>>>(W1, w1hi, w1lo, n4);
        n4 = (size_t)ED * FD * HD / 4;
        convert_split<<<(unsigned)((n4 + 255) / 256), 256>>>(W2, w2hi, w2lo, n4);
    }

    // GEMM1: h = gelu(x @ W1[e] + b1[e]); K=1024, N=4096
    gemm_mma<HD, FD, true, true>
        <<<dim3(TOK / 128, FD / 256, ED), 256, SMEM_BYTES>>>(xhi, xlo, w1hi, w1lo, b1);
    // GEMM2: out = h @ W2[e] + b2[e]; K=4096, N=1024
    gemm_mma<FD, HD, false, false>
        <<<dim3(TOK / 128, HD / 256, ED), 256, SMEM_BYTES>>>(hhi, hlo, w2hi, w2lo, b2);

    cudaMemsetAsync(d_out, 0, (size_t)out_size * sizeof(float), 0);
    combine_kernel<<<NJOBS, 256>>>(x, ln_g, ln_b, y);
}

// round 8
// speedup vs baseline: 3.6395x; 1.2927x over previous
#include <cuda_runtime.h>
#include <cuda_fp16.h>
#include <math.h>
#include <stdint.h>

#define TOK   8192
#define HD    1024
#define FD    4096
#define ED    8
#define NJOBS (TOK * 2)

// ---------------- device scratch ----------------
__device__ __half g_xhi[(size_t)TOK * HD];
__device__ __half g_xlo[(size_t)TOK * HD];
__device__ __half g_w1hi[(size_t)ED * HD * FD];
__device__ __half g_w2hi[(size_t)ED * FD * HD];
__device__ __half g_hhi[(size_t)NJOBS * FD];
__device__ __half g_hlo[(size_t)NJOBS * FD];
__device__ float  g_obuf[(size_t)NJOBS * HD];
__device__ int    g_jobs_tok[NJOBS];
__device__ int    g_jobs_e[NJOBS];
__device__ float  g_jobs_p[NJOBS];
__device__ int    g_cnt[ED];
__device__ int    g_off[ED];
__device__ int    g_topk_e[NJOBS];
__device__ float  g_topk_p[NJOBS];

// ---------------- PTX helpers (sm_80-class only) ----------------
__device__ __forceinline__ uint32_t smem_u32(const void* p) {
    uint32_t a;
    asm("{ .reg .u64 t; cvta.to.shared.u64 t, %1; cvt.u32.u64 %0, t; }" : "=r"(a) : "l"(p));
    return a;
}
__device__ __forceinline__ void ldsm_x4(uint32_t* r, uint32_t addr) {
    asm volatile("ldmatrix.sync.aligned.m8n8.x4.shared.b16 {%0,%1,%2,%3}, [%4];"
        : "=r"(r[0]), "=r"(r[1]), "=r"(r[2]), "=r"(r[3]) : "r"(addr));
}
__device__ __forceinline__ void ldsm_x4_t(uint32_t* r, uint32_t addr) {
    asm volatile("ldmatrix.sync.aligned.m8n8.x4.trans.shared.b16 {%0,%1,%2,%3}, [%4];"
        : "=r"(r[0]), "=r"(r[1]), "=r"(r[2]), "=r"(r[3]) : "r"(addr));
}
__device__ __forceinline__ void mma16816(float* d, const uint32_t* a, const uint32_t* b) {
    asm volatile("mma.sync.aligned.m16n8k16.row.col.f32.f16.f16.f32 "
        "{%0,%1,%2,%3}, {%4,%5,%6,%7}, {%8,%9}, {%0,%1,%2,%3};"
        : "+f"(d[0]), "+f"(d[1]), "+f"(d[2]), "+f"(d[3])
        : "r"(a[0]), "r"(a[1]), "r"(a[2]), "r"(a[3]), "r"(b[0]), "r"(b[1]));
}
__device__ __forceinline__ void cp16(uint32_t dst, const void* src) {
    asm volatile("cp.async.cg.shared.global [%0], [%1], 16;"
        :: "r"(dst), "l"(__cvta_generic_to_global(src)) : "memory");
}
#define CP_COMMIT() asm volatile("cp.async.commit_group;" ::: "memory")
#define CP_WAIT(n)  asm volatile("cp.async.wait_group %0;" :: "n"(n) : "memory")

// ---------------- reductions ----------------
__device__ __forceinline__ float block_reduce_sum(float v, float* red) {
    int tid = threadIdx.x;
    red[tid] = v;
    __syncthreads();
#pragma unroll
    for (int o = 128; o > 0; o >>= 1) {
        if (tid < o) red[tid] += red[tid + o];
        __syncthreads();
    }
    float r = red[0];
    __syncthreads();
    return r;
}

// ---------------- kernel 0: gating (no atomics; counts done in finalize) ----------------
__global__ void gate_kernel(const float* __restrict__ x,
                            const float* __restrict__ gn_g,
                            const float* __restrict__ gn_b,
                            const float* __restrict__ gate_w,
                            const float* __restrict__ gate_b) {
    int t = blockIdx.x, tid = threadIdx.x;
    const float4* xr4 = (const float4*)(x + (size_t)t * HD);
    __shared__ float red[256];
    __shared__ float sm_mean, sm_rstd;
    __shared__ float sm_logits[ED];

    float4 xv = xr4[tid];
    float xs[4] = {xv.x, xv.y, xv.z, xv.w};
    float s = 0.f, s2 = 0.f;
#pragma unroll
    for (int i = 0; i < 4; i++) { s += xs[i]; s2 += xs[i] * xs[i]; }
    float tot = block_reduce_sum(s, red);
    if (tid == 0) sm_mean = tot * (1.f / HD);
    float tot2 = block_reduce_sum(s2, red);
    if (tid == 0) {
        float m = sm_mean;
        sm_rstd = rsqrtf(tot2 * (1.f / HD) - m * m + 1e-5f);
    }
    __syncthreads();
    float m = sm_mean, r = sm_rstd;
    float acc[ED];
#pragma unroll
    for (int e = 0; e < ED; e++) acc[e] = 0.f;
#pragma unroll
    for (int i = 0; i < 4; i++) {
        int h = tid * 4 + i;
        float xn = (xs[i] - m) * r * gn_g[h] + gn_b[h];
#pragma unroll
        for (int e = 0; e < ED; e++) acc[e] += xn * gate_w[h * ED + e];
    }
#pragma unroll
    for (int e = 0; e < ED; e++) {
        float le = block_reduce_sum(acc[e], red);
        if (tid == 0) sm_logits[e] = le + gate_b[e];
    }
    __syncthreads();
    if (tid == 0) {
        float l[ED], pr[ED];
        float mx = -1e30f;
#pragma unroll
        for (int e = 0; e < ED; e++) { l[e] = sm_logits[e]; mx = fmaxf(mx, l[e]); }
        float ssum = 0.f;
#pragma unroll
        for (int e = 0; e < ED; e++) { pr[e] = expf(l[e] - mx); ssum += pr[e]; }
        float inv = 1.f / ssum;
#pragma unroll
        for (int e = 0; e < ED; e++) pr[e] *= inv;
        int i0 = 0;
#pragma unroll
        for (int e = 1; e < ED; e++) if (pr[e] > pr[i0]) i0 = e;
        int i1 = (i0 == 0) ? 1 : 0;
#pragma unroll
        for (int e = 0; e < ED; e++) if (e != i0 && pr[e] > pr[i1]) i1 = e;
        float p0 = pr[i0], p1 = pr[i1];
        float dn = 1.f / (p0 + p1 + 1e-9f);
        g_topk_e[t * 2 + 0] = i0;  g_topk_p[t * 2 + 0] = p0 * dn;
        g_topk_e[t * 2 + 1] = i1;  g_topk_p[t * 2 + 1] = p1 * dn;
    }
}

// ---------------- kernel 1: finalize routing (count + scan + scatter, 1 block) ----------------
__global__ void __launch_bounds__(1024) finalize_kernel() {
    __shared__ int scnt[ED], soff[ED], sfill[ED];
    int tid = threadIdx.x;
    if (tid < ED) { scnt[tid] = 0; sfill[tid] = 0; }
    __syncthreads();
    for (int j = tid; j < NJOBS; j += 1024) atomicAdd(&scnt[g_topk_e[j]], 1);
    __syncthreads();
    if (tid == 0) {
        int o = 0;
        for (int e = 0; e < ED; e++) {
            soff[e] = o;
            g_off[e] = o;
            g_cnt[e] = scnt[e];
            o += scnt[e];
        }
    }
    __syncthreads();
    for (int j = tid; j < NJOBS; j += 1024) {
        int e = g_topk_e[j];
        int pos = atomicAdd(&sfill[e], 1);
        int jj = soff[e] + pos;
        g_jobs_tok[jj] = j >> 1;
        g_jobs_e[jj]   = e;
        g_jobs_p[jj]   = g_topk_p[j];
    }
}

// ---------------- kernel 2: all converts in one launch ----------------
// x -> (xhi, xlo) exact split; W1 -> w1hi round; W2 -> w2hi round.
#define NX4  ((size_t)TOK * HD / 4)
#define NW4  ((size_t)ED * HD * FD / 4)
__global__ void __launch_bounds__(256) convert_all(const float* __restrict__ x,
                                                   const float* __restrict__ W1,
                                                   const float* __restrict__ W2) {
    size_t i = (size_t)blockIdx.x * 256 + threadIdx.x;
    if (i < NX4) {
        float4 v = ((const float4*)x)[i];
        float f[4] = {v.x, v.y, v.z, v.w};
        uint32_t hw[2], lw[2];
#pragma unroll
        for (int q = 0; q < 2; q++) {
            __half h0 = __float2half_rn(f[2 * q]),     h1 = __float2half_rn(f[2 * q + 1]);
            __half l0 = __float2half_rn(f[2 * q]     - __half2float(h0));
            __half l1 = __float2half_rn(f[2 * q + 1] - __half2float(h1));
            hw[q] = (uint32_t)__half_as_ushort(h0) | ((uint32_t)__half_as_ushort(h1) << 16);
            lw[q] = (uint32_t)__half_as_ushort(l0) | ((uint32_t)__half_as_ushort(l1) << 16);
        }
        ((uint2*)g_xhi)[i] = make_uint2(hw[0], hw[1]);
        ((uint2*)g_xlo)[i] = make_uint2(lw[0], lw[1]);
    } else if (i < NX4 + 2 * NW4) {
        size_t j = i - NX4;
        const float4* src = (j < NW4) ? (const float4*)W1 : (const float4*)W2;
        __half* dst = (j < NW4) ? g_w1hi : g_w2hi;
        size_t jj = (j < NW4) ? j : j - NW4;
        float4 v = src[jj];
        uint32_t hw[2];
        __half h0 = __float2half_rn(v.x), h1 = __float2half_rn(v.y);
        __half h2 = __float2half_rn(v.z), h3 = __float2half_rn(v.w);
        hw[0] = (uint32_t)__half_as_ushort(h0) | ((uint32_t)__half_as_ushort(h1) << 16);
        hw[1] = (uint32_t)__half_as_ushort(h2) | ((uint32_t)__half_as_ushort(h3) << 16);
        ((uint2*)dst)[jj] = make_uint2(hw[0], hw[1]);
    }
}

// ---------------- 2-pass fp16-split grouped GEMM, 128m x 256n tile ----------------
// A exact hi/lo split; B hi only. Passes: A_hi*B_hi + A_lo*B_hi.
// 8 warps = 2m x 4n; acc[4][8][4] = 128 regs/thread.
// Stage = A 16KB (128 rows x 128B = [hi 32k | lo 32k]) + B 16KB (32 k x 512B).
// 4 stages = 128KB + 1KB hdr.
#define STAGES 4
#define STAGE_BYTES 32768
#define SMEM_BYTES (1024 + STAGES * STAGE_BYTES)

template <int KDIM, int NDIM, bool GATHER, bool DOGELU>
__global__ void __launch_bounds__(256, 1)
gemm_mma(const __half* __restrict__ Ahi,  // [rows][KDIM]
         const __half* __restrict__ Alo,
         const __half* __restrict__ Whi,  // [E][KDIM][NDIM]
         const float* __restrict__ bias) {
    int e   = blockIdx.z;
    int cnt = g_cnt[e];
    int m0  = blockIdx.x * 128;
    if (m0 >= cnt) return;
    int off = g_off[e];
    int n0  = blockIdx.y * 256;

    extern __shared__ __align__(1024) char smem[];
    uint32_t sb = smem_u32(smem);
    int tid = threadIdx.x, wid = tid >> 5, lane = tid & 31;
    int wm = wid >> 2, wn = wid & 3;   // 2m x 4n warp grid
    int* s_tok = (int*)smem;

    if (GATHER && tid < 128) {
        int r = (m0 + tid < cnt) ? tid : 0;
        s_tok[tid] = g_jobs_tok[off + m0 + r];
    }
    __syncthreads();

    const __half* We_hi = Whi + (size_t)e * KDIM * NDIM + n0;
    const float* be = bias + (size_t)e * NDIM;

    // ---- A producer: 4 chunks/thread (u = tid&7 const; rows r = tid/8 + q*32)
    int au = tid & 7;
    uint32_t aswz = 16u * (uint32_t)(au ^ ((tid >> 3) & 7));
    const __half* aplane = (au < 4) ? Ahi : Alo;
    int acol = (au & 3) * 8;
    const __half* asrc[4];
    uint32_t adst[4];
#pragma unroll
    for (int q = 0; q < 4; q++) {
        int r = (tid >> 3) + q * 32;
        int row;
        if (GATHER) row = s_tok[r];
        else { int rr = (m0 + r < cnt) ? r : 0; row = off + m0 + rr; }
        asrc[q] = aplane + (size_t)row * KDIM + acol;
        adst[q] = (uint32_t)(r * 128) + aswz;
    }
    // ---- B producer: 4 chunks/thread (hi plane only)
    int bu = tid & 31, bk0 = tid >> 5;
    uint32_t bswz = (uint32_t)((bu >> 3) * 128 + 16 * ((bu & 7) ^ (bk0 & 7)));
    const __half* bsrc_hi = We_hi + (size_t)bk0 * NDIM + bu * 8;

    auto issue = [&](int s, int it) {
        uint32_t base = sb + 1024 + s * STAGE_BYTES;
#pragma unroll
        for (int q = 0; q < 4; q++) cp16(base + adst[q], asrc[q] + it * 32);
        uint32_t bb = base + 16384;
        size_t koff = (size_t)it * 32 * NDIM;
#pragma unroll
        for (int qq = 0; qq < 4; qq++)
            cp16(bb + (uint32_t)((bk0 + qq * 8) * 512) + bswz,
                 bsrc_hi + koff + (size_t)(qq * 8) * NDIM);
    };

    float acc[32][4];
#pragma unroll
    for (int i = 0; i < 32; i++)
#pragma unroll
        for (int j = 0; j < 4; j++) acc[i][j] = 0.f;

    constexpr int KIT = KDIM / 32;
#pragma unroll
    for (int s = 0; s < STAGES - 1; s++) {
        issue(s, s);
        CP_COMMIT();
    }

    int rl = lane & 15, cg = lane >> 4;
    for (int it = 0; it < KIT; it++) {
        CP_WAIT(STAGES - 2);
        __syncthreads();
        uint32_t As = sb + 1024 + (it % STAGES) * STAGE_BYTES;
        uint32_t Bs = As + 16384;
#pragma unroll
        for (int jj = 0; jj < 2; jj++) {
            uint32_t afr[2][4][4];
#pragma unroll
            for (int asec = 0; asec < 2; asec++)
#pragma unroll
                for (int mt = 0; mt < 4; mt++) {
                    int r = wm * 64 + mt * 16 + rl;
                    ldsm_x4(afr[asec][mt],
                            As + r * 128 + 16 * ((asec * 4 + jj * 2 + cg) ^ (r & 7)));
                }
            int rB = jj * 16 + rl;
            uint32_t brow = Bs + rB * 512 + wn * 128;
            uint32_t bfr[4][4];
#pragma unroll
            for (int g = 0; g < 4; g++)
                ldsm_x4_t(bfr[g], brow + 16 * ((g * 2 + cg) ^ (rB & 7)));
#pragma unroll
            for (int asec = 0; asec < 2; asec++)
#pragma unroll
                for (int mt = 0; mt < 4; mt++)
#pragma unroll
                    for (int g = 0; g < 4; g++)
#pragma unroll
                        for (int hh = 0; hh < 2; hh++)
                            mma16816(acc[mt * 8 + g * 2 + hh], afr[asec][mt], &bfr[g][hh * 2]);
        }
        int nxt = it + STAGES - 1;
        if (nxt < KIT) issue(nxt % STAGES, nxt);
        CP_COMMIT();
    }

    // ---- epilogue ----
#pragma unroll
    for (int mt = 0; mt < 4; mt++) {
#pragma unroll
        for (int nt = 0; nt < 8; nt++) {
            float* d = acc[mt * 8 + nt];
            int nc = n0 + wn * 64 + nt * 8 + 2 * (lane & 3);
            float b0 = be[nc], b1 = be[nc + 1];
            int r0 = m0 + wm * 64 + mt * 16 + (lane >> 2);
            int r1 = r0 + 8;
            float c00 = d[0] + b0, c01 = d[1] + b1;
            float c10 = d[2] + b0, c11 = d[3] + b1;
            if (DOGELU) {
                c00 = 0.5f * c00 * (1.f + erff(c00 * 0.70710678118654752f));
                c01 = 0.5f * c01 * (1.f + erff(c01 * 0.70710678118654752f));
                c10 = 0.5f * c10 * (1.f + erff(c10 * 0.70710678118654752f));
                c11 = 0.5f * c11 * (1.f + erff(c11 * 0.70710678118654752f));
                auto wr = [&](int rr, float a, float b) {
                    size_t base = (size_t)(off + rr) * NDIM + nc;
                    __half h0 = __float2half_rn(a), h1 = __float2half_rn(b);
                    __half l0 = __float2half_rn(a - __half2float(h0));
                    __half l1 = __float2half_rn(b - __half2float(h1));
                    *(uint32_t*)(g_hhi + base) =
                        (uint32_t)__half_as_ushort(h0) | ((uint32_t)__half_as_ushort(h1) << 16);
                    *(uint32_t*)(g_hlo + base) =
                        (uint32_t)__half_as_ushort(l0) | ((uint32_t)__half_as_ushort(l1) << 16);
                };
                if (r0 < cnt) wr(r0, c00, c01);
                if (r1 < cnt) wr(r1, c10, c11);
            } else {
                if (r0 < cnt) *(float2*)(g_obuf + (size_t)(off + r0) * NDIM + nc) = make_float2(c00, c01);
                if (r1 < cnt) *(float2*)(g_obuf + (size_t)(off + r1) * NDIM + nc) = make_float2(c10, c11);
            }
        }
    }
}

// ---------------- combine: LN(out + residual) * p ----------------
__global__ void combine_kernel(const float* __restrict__ x,
                               const float* __restrict__ ln_g,
                               const float* __restrict__ ln_b,
                               float* __restrict__ y) {
    int j = blockIdx.x, tid = threadIdx.x;
    int t = g_jobs_tok[j];
    int e = g_jobs_e[j];
    float p = g_jobs_p[j];
    const float4* orow = (const float4*)(g_obuf + (size_t)j * HD);
    const float4* xrow = (const float4*)(x + (size_t)t * HD);
    __shared__ float red[256];
    __shared__ float sm_mean, sm_rstd;
    float4 ov = orow[tid];
    float4 xv = xrow[tid];
    float v[4] = {ov.x + xv.x, ov.y + xv.y, ov.z + xv.z, ov.w + xv.w};
    float s = 0.f, s2 = 0.f;
#pragma unroll
    for (int i = 0; i < 4; i++) { s += v[i]; s2 += v[i] * v[i]; }
    float tot = block_reduce_sum(s, red);
    if (tid == 0) sm_mean = tot * (1.f / HD);
    float tot2 = block_reduce_sum(s2, red);
    if (tid == 0) {
        float m = sm_mean;
        sm_rstd = rsqrtf(tot2 * (1.f / HD) - m * m + 1e-5f);
    }
    __syncthreads();
    float m = sm_mean, r = sm_rstd;
#pragma unroll
    for (int i = 0; i < 4; i++) {
        int h = tid * 4 + i;
        float o = (v[i] - m) * r * ln_g[(size_t)e * HD + h] + ln_b[(size_t)e * HD + h];
        atomicAdd(&y[(size_t)t * HD + h], o * p);
    }
}

// ---------------- launch ----------------
extern "C" void kernel_launch(void* const* d_in, const int* in_sizes, int n_in,
                              void* d_out, int out_size) {
    const float* x      = (const float*)d_in[0];
    const float* W1     = (const float*)d_in[1];
    const float* b1     = (const float*)d_in[2];
    const float* W2     = (const float*)d_in[3];
    const float* b2     = (const float*)d_in[4];
    const float* ln_g   = (const float*)d_in[5];
    const float* ln_b   = (const float*)d_in[6];
    const float* gn_g   = (const float*)d_in[7];
    const float* gn_b   = (const float*)d_in[8];
    const float* gate_w = (const float*)d_in[9];
    const float* gate_b = (const float*)d_in[10];
    float* y = (float*)d_out;

    __half *xhi, *xlo, *w1hi, *w2hi, *hhi, *hlo;
    cudaGetSymbolAddress((void**)&xhi,  g_xhi);
    cudaGetSymbolAddress((void**)&xlo,  g_xlo);
    cudaGetSymbolAddress((void**)&w1hi, g_w1hi);
    cudaGetSymbolAddress((void**)&w2hi, g_w2hi);
    cudaGetSymbolAddress((void**)&hhi,  g_hhi);
    cudaGetSymbolAddress((void**)&hlo,  g_hlo);

    cudaFuncSetAttribute(gemm_mma<HD, FD, true, true>,
                         cudaFuncAttributeMaxDynamicSharedMemorySize, SMEM_BYTES);
    cudaFuncSetAttribute(gemm_mma<FD, HD, false, false>,
                         cudaFuncAttributeMaxDynamicSharedMemorySize, SMEM_BYTES);

    // 0: gating; 1: routing finalize; 2: converts; 3: GEMM1 (ncu-captured slot)
    gate_kernel<<<TOK, 256>>>(x, gn_g, gn_b, gate_w, gate_b);
    finalize_kernel<<<1, 1024>>>();
    {
        size_t total = NX4 + 2 * NW4;
        convert_all<<<(unsigned)((total + 255) / 256), 256>>>(x, W1, W2);
    }
    // GEMM1: h = gelu(x @ W1[e] + b1[e]); K=1024, N=4096
    gemm_mma<HD, FD, true, true>
        <<<dim3(TOK / 128, FD / 256, ED), 256, SMEM_BYTES>>>(xhi, xlo, w1hi, b1);
    // GEMM2: out = h @ W2[e] + b2[e]; K=4096, N=1024
    gemm_mma<FD, HD, false, false>
        <<<dim3(TOK / 128, HD / 256, ED), 256, SMEM_BYTES>>>(hhi, hlo, w2hi, b2);

    cudaMemsetAsync(d_out, 0, (size_t)out_size * sizeof(float), 0);
    combine_kernel<<<NJOBS, 256>>>(x, ln_g, ln_b, y);
}